// round 13
// baseline (speedup 1.0000x reference)
#include <cuda_runtime.h>
#include <cuda_fp16.h>
#include <math.h>

#define NPTS 65536
#define NS   16
#define CH   128
#define EPSB 1e-5f
#define LOG2E 1.4426950408889634f

typedef unsigned long long ull;

__device__ __forceinline__ void cpasync16(unsigned dst, const void* src) {
    asm volatile("cp.async.ca.shared.global [%0],[%1],16;" :: "r"(dst), "l"(src));
}
__device__ __forceinline__ void cpcommit() {
    asm volatile("cp.async.commit_group;");
}
template<int N> __device__ __forceinline__ void cpwaitg() {
    asm volatile("cp.async.wait_group %0;" :: "n"(N));
}
__device__ __forceinline__ unsigned f2tf32(float f) {
    unsigned u; asm("cvt.rna.tf32.f32 %0,%1;" : "=r"(u) : "f"(f)); return u;
}
__device__ __forceinline__ unsigned bf16x2hl(float hi, float lo) {
    unsigned d; asm("cvt.rn.bf16x2.f32 %0,%1,%2;" : "=r"(d) : "f"(hi), "f"(lo)); return d;
}
__device__ __forceinline__ unsigned f16x2hl(float hi, float lo) {
    unsigned d; asm("cvt.rn.f16x2.f32 %0,%1,%2;" : "=r"(d) : "f"(hi), "f"(lo)); return d;
}
__device__ __forceinline__ float bflo(unsigned u) {
    return __uint_as_float(u << 16);
}
__device__ __forceinline__ float bfhi(unsigned u) {
    return __uint_as_float(u & 0xffff0000u);
}
__device__ __forceinline__ ull packuu(unsigned lo, unsigned hi) {
    ull r; asm("mov.b64 %0,{%1,%2};" : "=l"(r) : "r"(lo), "r"(hi)); return r;
}
__device__ __forceinline__ void unpackuu(ull v, unsigned& lo, unsigned& hi) {
    asm("mov.b64 {%0,%1},%2;" : "=r"(lo), "=r"(hi) : "l"(v));
}
__device__ __forceinline__ void mma_tf32(float c[4],
                                         unsigned a0, unsigned a1,
                                         unsigned a2, unsigned a3,
                                         unsigned b0, unsigned b1) {
    asm("mma.sync.aligned.m16n8k8.row.col.f32.tf32.tf32.f32 "
        "{%0,%1,%2,%3},{%4,%5,%6,%7},{%8,%9},{%0,%1,%2,%3};"
        : "+f"(c[0]), "+f"(c[1]), "+f"(c[2]), "+f"(c[3])
        : "r"(a0), "r"(a1), "r"(a2), "r"(a3), "r"(b0), "r"(b1));
}
__device__ __forceinline__ void mma_bf16(float c[4],
                                         unsigned a0, unsigned a1,
                                         unsigned a2, unsigned a3,
                                         unsigned b0, unsigned b1) {
    asm("mma.sync.aligned.m16n8k16.row.col.f32.bf16.bf16.f32 "
        "{%0,%1,%2,%3},{%4,%5,%6,%7},{%8,%9},{%0,%1,%2,%3};"
        : "+f"(c[0]), "+f"(c[1]), "+f"(c[2]), "+f"(c[3])
        : "r"(a0), "r"(a1), "r"(a2), "r"(a3), "r"(b0), "r"(b1));
}

// static device scratch (allocation-guard safe)
__device__ float  g_q   [(size_t)NPTS * CH];
__device__ ull    g_kv16[(size_t)NPTS * 64];   // per (pt,lane): [K bf16 ull][V fp16 ull]
__device__ float4 g_p4  [NPTS];

// ---------------------------------------------------------------------------
__global__ void prep_kernel(const float* __restrict__ p)
{
    int i = blockIdx.x * 256 + threadIdx.x;
    g_p4[i] = make_float4(p[3 * i + 0], p[3 * i + 1], p[3 * i + 2], 0.f);
}

// ---------------------------------------------------------------------------
// Kernel 1: QKV GEMM on tensor cores. Paired-k smem (LDS.64 operand loads).
// Q -> g_q fp32; K -> g_kv16[.].even (bf16); V -> g_kv16[.].odd (fp16).
// ---------------------------------------------------------------------------
__global__ void __launch_bounds__(256)
qkv_tc_kernel(const float* __restrict__ x,
              const float* __restrict__ wq, const float* __restrict__ bq,
              const float* __restrict__ wk, const float* __restrict__ bk,
              const float* __restrict__ wv, const float* __restrict__ bv)
{
    // paired layout: entry e = 4*s + t holds tf32 pair (k = 8s+t, 8s+t+4)
    __shared__ ull X2[128][20];
    __shared__ ull W2[128][20];

    const float* W;
    const float* bias;
    const int sel = blockIdx.y;
    if (sel == 0)      { W = wq; bias = bq; }
    else if (sel == 1) { W = wk; bias = bk; }
    else               { W = wv; bias = bv; }

    const int tid  = threadIdx.x;
    const int warp = tid >> 5;
    const int lane = tid & 31;
    const int gid  = lane >> 2;
    const int tig  = lane & 3;
    const int m0   = blockIdx.x * 128;
    const int r0   = warp * 16;

    const int srow = tid >> 1;
    const int skq  = (tid & 1) * 16;
    const int e0   = (skq >> 3) * 4;     // 0 or 8 (first pair-entry index)

    float c[16][4];
#pragma unroll
    for (int nb = 0; nb < 16; ++nb)
#pragma unroll
        for (int j = 0; j < 4; ++j) c[nb][j] = 0.f;

#pragma unroll 1
    for (int ch = 0; ch < 4; ++ch) {
        // stage chunk: 16 values/thread -> 8 paired ull writes each for X and W
        {
            float xv[16], wv[16];
#pragma unroll
            for (int i = 0; i < 4; ++i) {
                float4 a = *(const float4*)&x[(size_t)(m0 + srow) * 128 + ch * 32 + skq + 4 * i];
                float4 b = *(const float4*)&W[(size_t)srow * 128 + ch * 32 + skq + 4 * i];
                xv[4 * i] = a.x; xv[4 * i + 1] = a.y; xv[4 * i + 2] = a.z; xv[4 * i + 3] = a.w;
                wv[4 * i] = b.x; wv[4 * i + 1] = b.y; wv[4 * i + 2] = b.z; wv[4 * i + 3] = b.w;
            }
#pragma unroll
            for (int j = 0; j < 4; ++j) {
                X2[srow][e0 + j]     = packuu(f2tf32(xv[j]),     f2tf32(xv[j + 4]));
                X2[srow][e0 + 4 + j] = packuu(f2tf32(xv[8 + j]), f2tf32(xv[12 + j]));
                W2[srow][e0 + j]     = packuu(f2tf32(wv[j]),     f2tf32(wv[j + 4]));
                W2[srow][e0 + 4 + j] = packuu(f2tf32(wv[8 + j]), f2tf32(wv[12 + j]));
            }
        }
        __syncthreads();

#pragma unroll
        for (int ks = 0; ks < 4; ++ks) {
            const int e = 4 * ks + tig;
            unsigned a0, a2, a1, a3;
            unpackuu(X2[r0 + gid][e],     a0, a2);
            unpackuu(X2[r0 + gid + 8][e], a1, a3);
#pragma unroll
            for (int nb = 0; nb < 16; ++nb) {
                unsigned b0, b1;
                unpackuu(W2[nb * 8 + gid][e], b0, b1);
                mma_tf32(c[nb], a0, a1, a2, a3, b0, b1);
            }
        }
        __syncthreads();
    }

    if (sel == 0) {
#pragma unroll
        for (int nb = 0; nb < 16; ++nb) {
            const int col = nb * 8 + 2 * tig;
            const float2 bv = *(const float2*)&bias[col];
            const size_t row = (size_t)(m0 + r0 + gid);
            *(float2*)&g_q[row * 128 + col] =
                make_float2(c[nb][0] + bv.x, c[nb][1] + bv.y);
            *(float2*)&g_q[(row + 8) * 128 + col] =
                make_float2(c[nb][2] + bv.x, c[nb][3] + bv.y);
        }
    } else if (sel == 1) {
        // K bf16 -> even ull of g_kv16
#pragma unroll
        for (int nb = 0; nb < 4; ++nb)
#pragma unroll
            for (int e = 0; e < 2; ++e) {
                const int l = nb * 8 + 2 * tig + e;
                const float b0 = bias[l], b1 = bias[l + 32];
                const float b2 = bias[l + 64], b3 = bias[l + 96];
                unsigned lo = bf16x2hl(c[nb + 4][e] + b1, c[nb][e] + b0);
                unsigned hi = bf16x2hl(c[nb + 12][e] + b3, c[nb + 8][e] + b2);
                g_kv16[2 * ((size_t)(m0 + r0 + gid) * 32 + l)] = ((ull)hi << 32) | lo;
                unsigned lo2 = bf16x2hl(c[nb + 4][e + 2] + b1, c[nb][e + 2] + b0);
                unsigned hi2 = bf16x2hl(c[nb + 12][e + 2] + b3, c[nb + 8][e + 2] + b2);
                g_kv16[2 * ((size_t)(m0 + r0 + gid + 8) * 32 + l)] = ((ull)hi2 << 32) | lo2;
            }
    } else {
        // V fp16 -> odd ull of g_kv16
#pragma unroll
        for (int nb = 0; nb < 4; ++nb)
#pragma unroll
            for (int e = 0; e < 2; ++e) {
                const int l = nb * 8 + 2 * tig + e;
                const float b0 = bias[l], b1 = bias[l + 32];
                const float b2 = bias[l + 64], b3 = bias[l + 96];
                unsigned lo = f16x2hl(c[nb + 4][e] + b1, c[nb][e] + b0);
                unsigned hi = f16x2hl(c[nb + 12][e] + b3, c[nb + 8][e] + b2);
                g_kv16[2 * ((size_t)(m0 + r0 + gid) * 32 + l) + 1] = ((ull)hi << 32) | lo;
                unsigned lo2 = f16x2hl(c[nb + 4][e + 2] + b1, c[nb][e + 2] + b0);
                unsigned hi2 = f16x2hl(c[nb + 12][e + 2] + b3, c[nb + 8][e + 2] + b2);
                g_kv16[2 * ((size_t)(m0 + r0 + gid + 8) * 32 + l) + 1] = ((ull)hi2 << 32) | lo2;
            }
    }
}

// ---------------------------------------------------------------------------
// Kernel 2: tensor-core attention (R12 structure, single fused KV ring).
// ---------------------------------------------------------------------------
#define PPW 8
// smem offsets (bytes)
#define OFF_KVR 0        // uint4 [16][4][32]     = 32768 (K ull | V ull)
#define OFF_WSM 32768    // unsigned [4][16][68]  = 17408
#define OFF_TT  50176    // float4 [4][16]        = 1024
#define OFF_WT  51200    // float [4][16][20]     = 5120
#define SMEM_ATTN 56320

__global__ void __launch_bounds__(128, 4)
attn_kernel(const int* __restrict__ idx,
            const float* __restrict__ pw1, const float* __restrict__ pb1,
            const float* __restrict__ pbng, const float* __restrict__ pbnb,
            const float* __restrict__ pbnm, const float* __restrict__ pbnv,
            const float* __restrict__ pw2, const float* __restrict__ pb2,
            const float* __restrict__ bn1g, const float* __restrict__ bn1b,
            const float* __restrict__ bn1m, const float* __restrict__ bn1v,
            const float* __restrict__ ww1, const float* __restrict__ wb1,
            const float* __restrict__ bn2g, const float* __restrict__ bn2b,
            const float* __restrict__ bn2m, const float* __restrict__ bn2v,
            const float* __restrict__ ww2, const float* __restrict__ wb2,
            float* __restrict__ out)
{
    extern __shared__ char dsm[];
    ull*      kvr = (ull*)(dsm + OFF_KVR);     // 2 ull per slot: [K][V]
    unsigned* wsm = (unsigned*)(dsm + OFF_WSM);
    float4*   ttb = (float4*)(dsm + OFF_TT);
    float*    wtb = (float*)(dsm + OFF_WT);

    const int lane = threadIdx.x & 31;
    const int w    = (threadIdx.x >> 5) & 3;
    const int gw   = blockIdx.x * (blockDim.x >> 5) + (threadIdx.x >> 5);
    const int gid  = lane >> 2;
    const int tig  = lane & 3;
    const int o    = lane & 15;

    // W1 bf16 B-fragments (R9-proven mapping)
    unsigned bw1[8][2][2];
#pragma unroll
    for (int s = 0; s < 8; ++s)
#pragma unroll
        for (int b = 0; b < 2; ++b)
#pragma unroll
            for (int j = 0; j < 2; ++j) {
                int p = 8 * s + tig + 4 * j;
                int c = (p < 32) ? p : p + 32;
                int oo = 8 * b + gid;
                bw1[s][b][j] = bf16x2hl(ww1[oo * CH + c + 32], ww1[oo * CH + c]);
            }

    // W2 tf32 B-fragments (LOG2E folded)
    unsigned w2f[2][2][2];
#pragma unroll
    for (int s = 0; s < 2; ++s)
#pragma unroll
        for (int b = 0; b < 2; ++b)
#pragma unroll
            for (int j = 0; j < 2; ++j) {
                int u = 8 * s + tig + 4 * j;
                int oo = 8 * b + gid;
                w2f[s][b][j] = f2tf32(ww2[oo * 16 + u] * LOG2E);
            }

    // BN2 constants on c-frag cols
    float s2c[4], b2c[4];
#pragma unroll
    for (int j = 0; j < 4; ++j) {
        int u = 2 * tig + (j & 1) + 8 * (j >> 1);
        float s = bn2g[u] * rsqrtf(bn2v[u] + EPSB);
        s2c[j] = s;
        b2c[j] = bn2b[u] - bn2m[u] * s + wb1[u] * s;
    }

    float s1[4], b1f[4], pw2v[4][3], pb2v[4];
#pragma unroll
    for (int r = 0; r < 4; ++r) {
        int c = lane + 32 * r;
        float s = bn1g[c] * rsqrtf(bn1v[c] + EPSB);
        s1[r]  = s;
        b1f[r] = bn1b[c] - bn1m[c] * s;
        pw2v[r][0] = pw2[c * 3 + 0];
        pw2v[r][1] = pw2[c * 3 + 1];
        pw2v[r][2] = pw2[c * 3 + 2];
        pb2v[r] = pb2[c];
    }
    float Af[9], df[3];
#pragma unroll
    for (int a = 0; a < 3; ++a) {
        float s  = pbng[a] * rsqrtf(pbnv[a] + EPSB);
        float sh = pbnb[a] - pbnm[a] * s;
#pragma unroll
        for (int b = 0; b < 3; ++b) Af[a * 3 + b] = s * pw1[a * 3 + b];
        df[a] = s * pb1[a] + sh;
    }

    const unsigned kv0 =
        (unsigned)__cvta_generic_to_shared(&kvr[2 * ((0 * 4 + w) * 32 + lane)]);

#pragma unroll 1
    for (int t = 0; t < PPW; ++t) {
        const int i = gw * PPW + t;

        const float4 pi = g_p4[i];
        float xqf[4];
#pragma unroll
        for (int r = 0; r < 4; ++r) {
            float xq = g_q[(size_t)i * CH + lane + 32 * r];
            xqf[r] = b1f[r] - s1[r] * xq;
        }
        const int myj = idx[i * NS + o];
        const float4 pjall = g_p4[myj];

        // issue all 16 neighbors' fused K+V loads (8 groups of 2)
#pragma unroll
        for (int g = 0; g < 8; ++g) {
#pragma unroll
            for (int e = 0; e < 2; ++e) {
                int n = 2 * g + e;
                int js = __shfl_sync(0xffffffffu, myj, n);
                cpasync16(kv0 + (unsigned)n * 2048u,
                          &g_kv16[2 * ((size_t)js * 32 + lane)]);
            }
            cpcommit();
        }

        // ---------------- Phase 1: consume K, build wsm + ttb ----------------
        auto body = [&](int n) {
            ull kk = kvr[2 * ((n * 4 + w) * 32 + lane)];
            unsigned klo, khi;
            unpackuu(kk, klo, khi);
            float gk[4] = {bflo(klo), bfhi(klo), bflo(khi), bfhi(khi)};
            float pr0 = __shfl_sync(0xffffffffu, pjall.x, n) - pi.x;
            float pr1 = __shfl_sync(0xffffffffu, pjall.y, n) - pi.y;
            float pr2 = __shfl_sync(0xffffffffu, pjall.z, n) - pi.z;

            float tt[3];
#pragma unroll
            for (int a = 0; a < 3; ++a) {
                float v = fmaf(pr2, Af[a * 3 + 2],
                          fmaf(pr1, Af[a * 3 + 1],
                          fmaf(pr0, Af[a * 3 + 0], df[a])));
                tt[a] = fmaxf(v, 0.f);
            }
            if (lane == 0)
                ttb[w * 16 + n] = make_float4(tt[0], tt[1], tt[2], 0.f);

            float wp[4];
#pragma unroll
            for (int r = 0; r < 4; ++r) {
                float pe = fmaf(tt[2], pw2v[r][2],
                           fmaf(tt[1], pw2v[r][1],
                           fmaf(tt[0], pw2v[r][0], pb2v[r])));
                wp[r] = fmaxf(fmaf(gk[r] + pe, s1[r], xqf[r]), 0.f);
            }
            wsm[(w * 16 + n) * 68 + lane]      = bf16x2hl(wp[1], wp[0]);
            wsm[(w * 16 + n) * 68 + 32 + lane] = bf16x2hl(wp[3], wp[2]);
        };
        cpwaitg<7>(); body(0);  body(1);
        cpwaitg<6>(); body(2);  body(3);
        cpwaitg<5>(); body(4);  body(5);
        cpwaitg<4>(); body(6);  body(7);
        cpwaitg<3>(); body(8);  body(9);
        cpwaitg<2>(); body(10); body(11);
        cpwaitg<1>(); body(12); body(13);
        cpwaitg<0>(); body(14); body(15);
        __syncwarp();

        // ---------------- Phase 2: tensor-core logits ----------------
        float c1[2][4] = {{0.f, 0.f, 0.f, 0.f}, {0.f, 0.f, 0.f, 0.f}};
#pragma unroll
        for (int s = 0; s < 8; ++s) {
            unsigned a0 = wsm[(w * 16 + gid)     * 68 + 8 * s + tig];
            unsigned a1 = wsm[(w * 16 + gid + 8) * 68 + 8 * s + tig];
            unsigned a2 = wsm[(w * 16 + gid)     * 68 + 8 * s + tig + 4];
            unsigned a3 = wsm[(w * 16 + gid + 8) * 68 + 8 * s + tig + 4];
            mma_bf16(c1[0], a0, a1, a2, a3, bw1[s][0][0], bw1[s][0][1]);
            mma_bf16(c1[1], a0, a1, a2, a3, bw1[s][1][0], bw1[s][1][1]);
        }

        // BN2 + ReLU
        float t1[2][4];
#pragma unroll
        for (int b = 0; b < 2; ++b)
#pragma unroll
            for (int q = 0; q < 4; ++q)
                t1[b][q] = fmaxf(fmaf(c1[b][q], s2c[(q & 1) + 2 * b],
                                      b2c[(q & 1) + 2 * b]), 0.f);

        // permute c-frag -> A-frag for GEMV2
        const int srcA = 4 * gid + (tig >> 1);
        const bool oddt = (tig & 1);
        unsigned aa[2][4];
#pragma unroll
        for (int s = 0; s < 2; ++s) {
            float v0 = __shfl_sync(0xffffffffu, t1[s][0], srcA);
            float v1 = __shfl_sync(0xffffffffu, t1[s][1], srcA);
            float v2 = __shfl_sync(0xffffffffu, t1[s][2], srcA);
            float v3 = __shfl_sync(0xffffffffu, t1[s][3], srcA);
            float u0v = oddt ? v1 : v0;
            float u1v = oddt ? v3 : v2;
            float q0 = __shfl_sync(0xffffffffu, t1[s][0], srcA + 2);
            float q1 = __shfl_sync(0xffffffffu, t1[s][1], srcA + 2);
            float q2 = __shfl_sync(0xffffffffu, t1[s][2], srcA + 2);
            float q3 = __shfl_sync(0xffffffffu, t1[s][3], srcA + 2);
            float u2v = oddt ? q1 : q0;
            float u3v = oddt ? q3 : q2;
            aa[s][0] = f2tf32(u0v); aa[s][1] = f2tf32(u1v);
            aa[s][2] = f2tf32(u2v); aa[s][3] = f2tf32(u3v);
        }

        float c2[2][4] = {{0.f, 0.f, 0.f, 0.f}, {0.f, 0.f, 0.f, 0.f}};
#pragma unroll
        for (int s = 0; s < 2; ++s) {
            mma_tf32(c2[0], aa[s][0], aa[s][1], aa[s][2], aa[s][3],
                     w2f[s][0][0], w2f[s][0][1]);
            mma_tf32(c2[1], aa[s][0], aa[s][1], aa[s][2], aa[s][3],
                     w2f[s][1][0], w2f[s][1][1]);
        }

        // softmax over neighbors (fragment rows)
        float mx[2][2], Zs[2][2];
#pragma unroll
        for (int b = 0; b < 2; ++b) {
            mx[b][0] = fmaxf(c2[b][0], c2[b][2]);
            mx[b][1] = fmaxf(c2[b][1], c2[b][3]);
        }
#pragma unroll
        for (int msk = 4; msk <= 16; msk <<= 1)
#pragma unroll
            for (int b = 0; b < 2; ++b)
#pragma unroll
                for (int e = 0; e < 2; ++e)
                    mx[b][e] = fmaxf(mx[b][e],
                                     __shfl_xor_sync(0xffffffffu, mx[b][e], msk));
        float ev[2][4];
#pragma unroll
        for (int b = 0; b < 2; ++b)
#pragma unroll
            for (int q = 0; q < 4; ++q)
                ev[b][q] = exp2f(c2[b][q] - mx[b][q & 1]);
#pragma unroll
        for (int b = 0; b < 2; ++b) {
            Zs[b][0] = ev[b][0] + ev[b][2];
            Zs[b][1] = ev[b][1] + ev[b][3];
        }
#pragma unroll
        for (int msk = 4; msk <= 16; msk <<= 1)
#pragma unroll
            for (int b = 0; b < 2; ++b)
#pragma unroll
                for (int e = 0; e < 2; ++e)
                    Zs[b][e] += __shfl_xor_sync(0xffffffffu, Zs[b][e], msk);

        // exp weights transposed to wtb[o][n]
#pragma unroll
        for (int b = 0; b < 2; ++b)
#pragma unroll
            for (int q = 0; q < 4; ++q)
                wtb[(w * 16 + 2 * tig + (q & 1) + 8 * b) * 20 + gid + 8 * (q >> 1)] = ev[b][q];

        // unnormalized Z for this lane's column
        const int zsrc = (lane & 7) >> 1;
        float z00 = __shfl_sync(0xffffffffu, Zs[0][0], zsrc);
        float z01 = __shfl_sync(0xffffffffu, Zs[0][1], zsrc);
        float z10 = __shfl_sync(0xffffffffu, Zs[1][0], zsrc);
        float z11 = __shfl_sync(0xffffffffu, Zs[1][1], zsrc);
        float ze0 = (lane & 1) ? z01 : z00;
        float ze1 = (lane & 1) ? z11 : z10;
        float Zm  = (lane & 8) ? ze1 : ze0;
        float invZ = __frcp_rn(Zm);
        __syncwarp();

        // ------------- V accumulation from fused ring + tt fold -------------
        float Acc[4] = {0.f, 0.f, 0.f, 0.f};
        float st0 = 0.f, st1 = 0.f, st2 = 0.f;
#pragma unroll
        for (int h = 0; h < 4; ++h) {
            float4 wq4 = *(const float4*)&wtb[(w * 16 + o) * 20 + 4 * h];
#pragma unroll
            for (int j = 0; j < 4; ++j) {
                int n = 4 * h + j;
                float wn = (j == 0) ? wq4.x : (j == 1) ? wq4.y : (j == 2) ? wq4.z : wq4.w;
                ull vv = kvr[2 * ((n * 4 + w) * 32 + lane) + 1];
                unsigned vlo, vhi;
                unpackuu(vv, vlo, vhi);
                float2 f0 = __half22float2(*(const __half2*)&vlo);
                float2 f1 = __half22float2(*(const __half2*)&vhi);
                float4 t4 = ttb[w * 16 + n];
                Acc[0] = fmaf(wn, f0.x, Acc[0]);
                Acc[1] = fmaf(wn, f0.y, Acc[1]);
                Acc[2] = fmaf(wn, f1.x, Acc[2]);
                Acc[3] = fmaf(wn, f1.y, Acc[3]);
                st0 = fmaf(wn, t4.x, st0);
                st1 = fmaf(wn, t4.y, st1);
                st2 = fmaf(wn, t4.z, st2);
            }
        }

#pragma unroll
        for (int r = 0; r < 4; ++r) {
            float pesum = fmaf(pw2v[r][2], st2,
                          fmaf(pw2v[r][1], st1,
                          fmaf(pw2v[r][0], st0, pb2v[r] * Zm)));
            out[(size_t)i * CH + lane + 32 * r] = (Acc[r] + pesum) * invZ;
        }
    }
}

// ---------------------------------------------------------------------------
extern "C" void kernel_launch(void* const* d_in, const int* in_sizes, int n_in,
                              void* d_out, int out_size)
{
    const float* p    = (const float*)d_in[0];
    const float* x    = (const float*)d_in[1];
    const int*   idx  = (const int*)  d_in[2];
    const float* wq   = (const float*)d_in[3];
    const float* bq   = (const float*)d_in[4];
    const float* wk   = (const float*)d_in[5];
    const float* bk   = (const float*)d_in[6];
    const float* wv   = (const float*)d_in[7];
    const float* bv   = (const float*)d_in[8];
    const float* pw1  = (const float*)d_in[9];
    const float* pb1  = (const float*)d_in[10];
    const float* pbng = (const float*)d_in[11];
    const float* pbnb = (const float*)d_in[12];
    const float* pbnm = (const float*)d_in[13];
    const float* pbnv = (const float*)d_in[14];
    const float* pw2  = (const float*)d_in[15];
    const float* pb2  = (const float*)d_in[16];
    const float* bn1g = (const float*)d_in[17];
    const float* bn1b = (const float*)d_in[18];
    const float* bn1m = (const float*)d_in[19];
    const float* bn1v = (const float*)d_in[20];
    const float* ww1  = (const float*)d_in[21];
    const float* wb1  = (const float*)d_in[22];
    const float* bn2g = (const float*)d_in[23];
    const float* bn2b = (const float*)d_in[24];
    const float* bn2m = (const float*)d_in[25];
    const float* bn2v = (const float*)d_in[26];
    const float* ww2  = (const float*)d_in[27];
    const float* wb2  = (const float*)d_in[28];
    float* out = (float*)d_out;

    cudaFuncSetAttribute(attn_kernel,
                         cudaFuncAttributeMaxDynamicSharedMemorySize, SMEM_ATTN);

    prep_kernel<<<NPTS / 256, 256>>>(p);
    qkv_tc_kernel<<<dim3(NPTS / 128, 3), 256>>>(x, wq, bq, wk, bk, wv, bv);

    attn_kernel<<<NPTS / (PPW * 4), 128, SMEM_ATTN>>>(
        idx,
        pw1, pb1, pbng, pbnb, pbnm, pbnv, pw2, pb2,
        bn1g, bn1b, bn1m, bn1v, ww1, wb1,
        bn2g, bn2b, bn2m, bn2v, ww2, wb2,
        out);
}

// round 14
// speedup vs baseline: 1.0732x; 1.0732x over previous
#include <cuda_runtime.h>
#include <cuda_fp16.h>
#include <math.h>

#define NPTS 65536
#define NS   16
#define CH   128
#define EPSB 1e-5f
#define LOG2E 1.4426950408889634f

typedef unsigned long long ull;

__device__ __forceinline__ void cpasync8(unsigned dst, const void* src) {
    asm volatile("cp.async.ca.shared.global [%0],[%1],8;" :: "r"(dst), "l"(src));
}
__device__ __forceinline__ void cpcommit() {
    asm volatile("cp.async.commit_group;");
}
template<int N> __device__ __forceinline__ void cpwaitg() {
    asm volatile("cp.async.wait_group %0;" :: "n"(N));
}
__device__ __forceinline__ unsigned f2tf32(float f) {
    unsigned u; asm("cvt.rna.tf32.f32 %0,%1;" : "=r"(u) : "f"(f)); return u;
}
__device__ __forceinline__ unsigned bf16x2hl(float hi, float lo) {
    unsigned d; asm("cvt.rn.bf16x2.f32 %0,%1,%2;" : "=r"(d) : "f"(hi), "f"(lo)); return d;
}
__device__ __forceinline__ unsigned f16x2hl(float hi, float lo) {
    unsigned d; asm("cvt.rn.f16x2.f32 %0,%1,%2;" : "=r"(d) : "f"(hi), "f"(lo)); return d;
}
__device__ __forceinline__ float bflo(unsigned u) {
    return __uint_as_float(u << 16);
}
__device__ __forceinline__ float bfhi(unsigned u) {
    return __uint_as_float(u & 0xffff0000u);
}
__device__ __forceinline__ void mma_tf32(float c[4],
                                         unsigned a0, unsigned a1,
                                         unsigned a2, unsigned a3,
                                         unsigned b0, unsigned b1) {
    asm("mma.sync.aligned.m16n8k8.row.col.f32.tf32.tf32.f32 "
        "{%0,%1,%2,%3},{%4,%5,%6,%7},{%8,%9},{%0,%1,%2,%3};"
        : "+f"(c[0]), "+f"(c[1]), "+f"(c[2]), "+f"(c[3])
        : "r"(a0), "r"(a1), "r"(a2), "r"(a3), "r"(b0), "r"(b1));
}
__device__ __forceinline__ void mma_bf16(float c[4],
                                         unsigned a0, unsigned a1,
                                         unsigned a2, unsigned a3,
                                         unsigned b0, unsigned b1) {
    asm("mma.sync.aligned.m16n8k16.row.col.f32.bf16.bf16.f32 "
        "{%0,%1,%2,%3},{%4,%5,%6,%7},{%8,%9},{%0,%1,%2,%3};"
        : "+f"(c[0]), "+f"(c[1]), "+f"(c[2]), "+f"(c[3])
        : "r"(a0), "r"(a1), "r"(a2), "r"(a3), "r"(b0), "r"(b1));
}

// static device scratch (allocation-guard safe)
__device__ float  g_q [(size_t)NPTS * CH];
__device__ ull    g_kb[(size_t)NPTS * 32];   // bf16 K packed: 256B/point
__device__ ull    g_vh[(size_t)NPTS * 32];   // fp16 V packed: 256B/point
__device__ float4 g_p4[NPTS];

// ---------------------------------------------------------------------------
__global__ void prep_kernel(const float* __restrict__ p)
{
    int i = blockIdx.x * 256 + threadIdx.x;
    g_p4[i] = make_float4(p[3 * i + 0], p[3 * i + 1], p[3 * i + 2], 0.f);
}

// ---------------------------------------------------------------------------
// Kernel 1: QKV GEMM on tensor cores (R12-exact). Q fp32, K bf16, V fp16.
// ---------------------------------------------------------------------------
__global__ void __launch_bounds__(256)
qkv_tc_kernel(const float* __restrict__ x,
              const float* __restrict__ wq, const float* __restrict__ bq,
              const float* __restrict__ wk, const float* __restrict__ bk,
              const float* __restrict__ wv, const float* __restrict__ bv)
{
    __shared__ unsigned Xs[128][36];
    __shared__ unsigned Ws[128][36];

    const float* W;
    const float* bias;
    const int sel = blockIdx.y;
    if (sel == 0)      { W = wq; bias = bq; }
    else if (sel == 1) { W = wk; bias = bk; }
    else               { W = wv; bias = bv; }

    const int tid  = threadIdx.x;
    const int warp = tid >> 5;
    const int lane = tid & 31;
    const int gid  = lane >> 2;
    const int tig  = lane & 3;
    const int m0   = blockIdx.x * 128;
    const int r0   = warp * 16;

    const int srow = tid >> 1;
    const int skq  = (tid & 1) * 16;

    float c[16][4];
#pragma unroll
    for (int nb = 0; nb < 16; ++nb)
#pragma unroll
        for (int j = 0; j < 4; ++j) c[nb][j] = 0.f;

#pragma unroll 1
    for (int ch = 0; ch < 4; ++ch) {
#pragma unroll
        for (int i = 0; i < 4; ++i) {
            float4 xv = *(const float4*)&x[(size_t)(m0 + srow) * 128 + ch * 32 + skq + 4 * i];
            float4 wv = *(const float4*)&W[(size_t)srow * 128 + ch * 32 + skq + 4 * i];
            uint4 xt, wt;
            xt.x = f2tf32(xv.x); xt.y = f2tf32(xv.y); xt.z = f2tf32(xv.z); xt.w = f2tf32(xv.w);
            wt.x = f2tf32(wv.x); wt.y = f2tf32(wv.y); wt.z = f2tf32(wv.z); wt.w = f2tf32(wv.w);
            *(uint4*)&Xs[srow][skq + 4 * i] = xt;
            *(uint4*)&Ws[srow][skq + 4 * i] = wt;
        }
        __syncthreads();

#pragma unroll
        for (int ks = 0; ks < 4; ++ks) {
            const int k = ks * 8;
            unsigned a0 = Xs[r0 + gid][k + tig];
            unsigned a1 = Xs[r0 + gid + 8][k + tig];
            unsigned a2 = Xs[r0 + gid][k + tig + 4];
            unsigned a3 = Xs[r0 + gid + 8][k + tig + 4];
#pragma unroll
            for (int nb = 0; nb < 16; ++nb) {
                unsigned b0 = Ws[nb * 8 + gid][k + tig];
                unsigned b1 = Ws[nb * 8 + gid][k + tig + 4];
                mma_tf32(c[nb], a0, a1, a2, a3, b0, b1);
            }
        }
        __syncthreads();
    }

    if (sel == 0) {
#pragma unroll
        for (int nb = 0; nb < 16; ++nb) {
            const int col = nb * 8 + 2 * tig;
            const float2 bv = *(const float2*)&bias[col];
            const size_t row = (size_t)(m0 + r0 + gid);
            *(float2*)&g_q[row * 128 + col] =
                make_float2(c[nb][0] + bv.x, c[nb][1] + bv.y);
            *(float2*)&g_q[(row + 8) * 128 + col] =
                make_float2(c[nb][2] + bv.x, c[nb][3] + bv.y);
        }
    } else if (sel == 1) {
        // K: bf16 packed per lane-slot l: {(k(l),k(l+32)),(k(l+64),k(l+96))}
#pragma unroll
        for (int nb = 0; nb < 4; ++nb)
#pragma unroll
            for (int e = 0; e < 2; ++e) {
                const int l = nb * 8 + 2 * tig + e;
                const float b0 = bias[l], b1 = bias[l + 32];
                const float b2 = bias[l + 64], b3 = bias[l + 96];
                unsigned lo = bf16x2hl(c[nb + 4][e] + b1, c[nb][e] + b0);
                unsigned hi = bf16x2hl(c[nb + 12][e] + b3, c[nb + 8][e] + b2);
                g_kb[(size_t)(m0 + r0 + gid) * 32 + l] = ((ull)hi << 32) | lo;
                unsigned lo2 = bf16x2hl(c[nb + 4][e + 2] + b1, c[nb][e + 2] + b0);
                unsigned hi2 = bf16x2hl(c[nb + 12][e + 2] + b3, c[nb + 8][e + 2] + b2);
                g_kb[(size_t)(m0 + r0 + gid + 8) * 32 + l] = ((ull)hi2 << 32) | lo2;
            }
    } else {
        // V: fp16 packed, same layout as K (single rounding)
#pragma unroll
        for (int nb = 0; nb < 4; ++nb)
#pragma unroll
            for (int e = 0; e < 2; ++e) {
                const int l = nb * 8 + 2 * tig + e;
                const float b0 = bias[l], b1 = bias[l + 32];
                const float b2 = bias[l + 64], b3 = bias[l + 96];
                unsigned lo = f16x2hl(c[nb + 4][e] + b1, c[nb][e] + b0);
                unsigned hi = f16x2hl(c[nb + 12][e] + b3, c[nb + 8][e] + b2);
                g_vh[(size_t)(m0 + r0 + gid) * 32 + l] = ((ull)hi << 32) | lo;
                unsigned lo2 = f16x2hl(c[nb + 4][e + 2] + b1, c[nb][e + 2] + b0);
                unsigned hi2 = f16x2hl(c[nb + 12][e + 2] + b3, c[nb + 8][e + 2] + b2);
                g_vh[(size_t)(m0 + r0 + gid + 8) * 32 + l] = ((ull)hi2 << 32) | lo2;
            }
    }
}

// ---------------------------------------------------------------------------
// Kernel 2: tensor-core attention (R12 structure; 4-wide phase-1 ILP windows).
// ---------------------------------------------------------------------------
#define PPW 8
// smem offsets (bytes)
#define OFF_KR  0        // ull [16][4][32]       = 16384
#define OFF_VR  16384    // ull [16][4][32]       = 16384
#define OFF_WSM 32768    // unsigned [4][16][68]  = 17408
#define OFF_TT  50176    // float4 [4][16]        = 1024
#define OFF_WT  51200    // float [4][16][20]     = 5120
#define SMEM_ATTN 56320

__global__ void __launch_bounds__(128, 4)
attn_kernel(const int* __restrict__ idx,
            const float* __restrict__ pw1, const float* __restrict__ pb1,
            const float* __restrict__ pbng, const float* __restrict__ pbnb,
            const float* __restrict__ pbnm, const float* __restrict__ pbnv,
            const float* __restrict__ pw2, const float* __restrict__ pb2,
            const float* __restrict__ bn1g, const float* __restrict__ bn1b,
            const float* __restrict__ bn1m, const float* __restrict__ bn1v,
            const float* __restrict__ ww1, const float* __restrict__ wb1,
            const float* __restrict__ bn2g, const float* __restrict__ bn2b,
            const float* __restrict__ bn2m, const float* __restrict__ bn2v,
            const float* __restrict__ ww2, const float* __restrict__ wb2,
            float* __restrict__ out)
{
    extern __shared__ char dsm[];
    ull*      krp = (ull*)(dsm + OFF_KR);
    ull*      vrp = (ull*)(dsm + OFF_VR);
    unsigned* wsm = (unsigned*)(dsm + OFF_WSM);
    float4*   ttb = (float4*)(dsm + OFF_TT);
    float*    wtb = (float*)(dsm + OFF_WT);

    const int lane = threadIdx.x & 31;
    const int w    = (threadIdx.x >> 5) & 3;
    const int gw   = blockIdx.x * (blockDim.x >> 5) + (threadIdx.x >> 5);
    const int gid  = lane >> 2;
    const int tig  = lane & 3;
    const int o    = lane & 15;

    // W1 bf16 B-fragments (R9-proven mapping)
    unsigned bw1[8][2][2];
#pragma unroll
    for (int s = 0; s < 8; ++s)
#pragma unroll
        for (int b = 0; b < 2; ++b)
#pragma unroll
            for (int j = 0; j < 2; ++j) {
                int p = 8 * s + tig + 4 * j;
                int c = (p < 32) ? p : p + 32;
                int oo = 8 * b + gid;
                bw1[s][b][j] = bf16x2hl(ww1[oo * CH + c + 32], ww1[oo * CH + c]);
            }

    // W2 tf32 B-fragments (LOG2E folded)
    unsigned w2f[2][2][2];
#pragma unroll
    for (int s = 0; s < 2; ++s)
#pragma unroll
        for (int b = 0; b < 2; ++b)
#pragma unroll
            for (int j = 0; j < 2; ++j) {
                int u = 8 * s + tig + 4 * j;
                int oo = 8 * b + gid;
                w2f[s][b][j] = f2tf32(ww2[oo * 16 + u] * LOG2E);
            }

    // BN2 constants on c-frag cols
    float s2c[4], b2c[4];
#pragma unroll
    for (int j = 0; j < 4; ++j) {
        int u = 2 * tig + (j & 1) + 8 * (j >> 1);
        float s = bn2g[u] * rsqrtf(bn2v[u] + EPSB);
        s2c[j] = s;
        b2c[j] = bn2b[u] - bn2m[u] * s + wb1[u] * s;
    }

    float s1[4], b1f[4], pw2v[4][3], pb2v[4];
#pragma unroll
    for (int r = 0; r < 4; ++r) {
        int c = lane + 32 * r;
        float s = bn1g[c] * rsqrtf(bn1v[c] + EPSB);
        s1[r]  = s;
        b1f[r] = bn1b[c] - bn1m[c] * s;
        pw2v[r][0] = pw2[c * 3 + 0];
        pw2v[r][1] = pw2[c * 3 + 1];
        pw2v[r][2] = pw2[c * 3 + 2];
        pb2v[r] = pb2[c];
    }
    float Af[9], df[3];
#pragma unroll
    for (int a = 0; a < 3; ++a) {
        float s  = pbng[a] * rsqrtf(pbnv[a] + EPSB);
        float sh = pbnb[a] - pbnm[a] * s;
#pragma unroll
        for (int b = 0; b < 3; ++b) Af[a * 3 + b] = s * pw1[a * 3 + b];
        df[a] = s * pb1[a] + sh;
    }

    const unsigned kr0 =
        (unsigned)__cvta_generic_to_shared(&krp[w * 32 + lane]);
    const unsigned vr0 =
        (unsigned)__cvta_generic_to_shared(&vrp[w * 32 + lane]);

#pragma unroll 1
    for (int t = 0; t < PPW; ++t) {
        const int i = gw * PPW + t;

        const float4 pi = g_p4[i];
        float xqf[4];
#pragma unroll
        for (int r = 0; r < 4; ++r) {
            float xq = g_q[(size_t)i * CH + lane + 32 * r];
            xqf[r] = b1f[r] - s1[r] * xq;
        }
        const int myj = idx[i * NS + o];
        const float4 pjall = g_p4[myj];

        // issue all 16 neighbors' K+V loads (4 commit groups of 4 neighbors)
#pragma unroll
        for (int g = 0; g < 4; ++g) {
#pragma unroll
            for (int e = 0; e < 4; ++e) {
                int n = 4 * g + e;
                int js = __shfl_sync(0xffffffffu, myj, n);
                cpasync8(kr0 + (unsigned)n * 1024u, &g_kb[(size_t)js * 32 + lane]);
                cpasync8(vr0 + (unsigned)n * 1024u, &g_vh[(size_t)js * 32 + lane]);
            }
            cpcommit();
        }

        // ---------------- Phase 1: consume K, build wsm + ttb ----------------
        auto body = [&](int n) {
            ull kk = krp[(n * 4 + w) * 32 + lane];
            unsigned klo = (unsigned)kk, khi = (unsigned)(kk >> 32);
            float gk[4] = {bflo(klo), bfhi(klo), bflo(khi), bfhi(khi)};
            float pr0 = __shfl_sync(0xffffffffu, pjall.x, n) - pi.x;
            float pr1 = __shfl_sync(0xffffffffu, pjall.y, n) - pi.y;
            float pr2 = __shfl_sync(0xffffffffu, pjall.z, n) - pi.z;

            float tt[3];
#pragma unroll
            for (int a = 0; a < 3; ++a) {
                float v = fmaf(pr2, Af[a * 3 + 2],
                          fmaf(pr1, Af[a * 3 + 1],
                          fmaf(pr0, Af[a * 3 + 0], df[a])));
                tt[a] = fmaxf(v, 0.f);
            }
            if (lane == 0)
                ttb[w * 16 + n] = make_float4(tt[0], tt[1], tt[2], 0.f);

            float wp[4];
#pragma unroll
            for (int r = 0; r < 4; ++r) {
                float pe = fmaf(tt[2], pw2v[r][2],
                           fmaf(tt[1], pw2v[r][1],
                           fmaf(tt[0], pw2v[r][0], pb2v[r])));
                wp[r] = fmaxf(fmaf(gk[r] + pe, s1[r], xqf[r]), 0.f);
            }
            wsm[(w * 16 + n) * 68 + lane]      = bf16x2hl(wp[1], wp[0]);
            wsm[(w * 16 + n) * 68 + 32 + lane] = bf16x2hl(wp[3], wp[2]);
        };
        cpwaitg<3>(); body(0);  body(1);  body(2);  body(3);
        cpwaitg<2>(); body(4);  body(5);  body(6);  body(7);
        cpwaitg<1>(); body(8);  body(9);  body(10); body(11);
        cpwaitg<0>(); body(12); body(13); body(14); body(15);
        __syncwarp();

        // ---------------- Phase 2: tensor-core logits ----------------
        float c1[2][4] = {{0.f, 0.f, 0.f, 0.f}, {0.f, 0.f, 0.f, 0.f}};
#pragma unroll
        for (int s = 0; s < 8; ++s) {
            unsigned a0 = wsm[(w * 16 + gid)     * 68 + 8 * s + tig];
            unsigned a1 = wsm[(w * 16 + gid + 8) * 68 + 8 * s + tig];
            unsigned a2 = wsm[(w * 16 + gid)     * 68 + 8 * s + tig + 4];
            unsigned a3 = wsm[(w * 16 + gid + 8) * 68 + 8 * s + tig + 4];
            mma_bf16(c1[0], a0, a1, a2, a3, bw1[s][0][0], bw1[s][0][1]);
            mma_bf16(c1[1], a0, a1, a2, a3, bw1[s][1][0], bw1[s][1][1]);
        }

        // BN2 + ReLU
        float t1[2][4];
#pragma unroll
        for (int b = 0; b < 2; ++b)
#pragma unroll
            for (int q = 0; q < 4; ++q)
                t1[b][q] = fmaxf(fmaf(c1[b][q], s2c[(q & 1) + 2 * b],
                                      b2c[(q & 1) + 2 * b]), 0.f);

        // permute c-frag -> A-frag for GEMV2
        const int srcA = 4 * gid + (tig >> 1);
        const bool oddt = (tig & 1);
        unsigned aa[2][4];
#pragma unroll
        for (int s = 0; s < 2; ++s) {
            float v0 = __shfl_sync(0xffffffffu, t1[s][0], srcA);
            float v1 = __shfl_sync(0xffffffffu, t1[s][1], srcA);
            float v2 = __shfl_sync(0xffffffffu, t1[s][2], srcA);
            float v3 = __shfl_sync(0xffffffffu, t1[s][3], srcA);
            float u0v = oddt ? v1 : v0;
            float u1v = oddt ? v3 : v2;
            float q0 = __shfl_sync(0xffffffffu, t1[s][0], srcA + 2);
            float q1 = __shfl_sync(0xffffffffu, t1[s][1], srcA + 2);
            float q2 = __shfl_sync(0xffffffffu, t1[s][2], srcA + 2);
            float q3 = __shfl_sync(0xffffffffu, t1[s][3], srcA + 2);
            float u2v = oddt ? q1 : q0;
            float u3v = oddt ? q3 : q2;
            aa[s][0] = f2tf32(u0v); aa[s][1] = f2tf32(u1v);
            aa[s][2] = f2tf32(u2v); aa[s][3] = f2tf32(u3v);
        }

        float c2[2][4] = {{0.f, 0.f, 0.f, 0.f}, {0.f, 0.f, 0.f, 0.f}};
#pragma unroll
        for (int s = 0; s < 2; ++s) {
            mma_tf32(c2[0], aa[s][0], aa[s][1], aa[s][2], aa[s][3],
                     w2f[s][0][0], w2f[s][0][1]);
            mma_tf32(c2[1], aa[s][0], aa[s][1], aa[s][2], aa[s][3],
                     w2f[s][1][0], w2f[s][1][1]);
        }

        // softmax over neighbors (fragment rows)
        float mx[2][2], Zs[2][2];
#pragma unroll
        for (int b = 0; b < 2; ++b) {
            mx[b][0] = fmaxf(c2[b][0], c2[b][2]);
            mx[b][1] = fmaxf(c2[b][1], c2[b][3]);
        }
#pragma unroll
        for (int msk = 4; msk <= 16; msk <<= 1)
#pragma unroll
            for (int b = 0; b < 2; ++b)
#pragma unroll
                for (int e = 0; e < 2; ++e)
                    mx[b][e] = fmaxf(mx[b][e],
                                     __shfl_xor_sync(0xffffffffu, mx[b][e], msk));
        float ev[2][4];
#pragma unroll
        for (int b = 0; b < 2; ++b)
#pragma unroll
            for (int q = 0; q < 4; ++q)
                ev[b][q] = exp2f(c2[b][q] - mx[b][q & 1]);
#pragma unroll
        for (int b = 0; b < 2; ++b) {
            Zs[b][0] = ev[b][0] + ev[b][2];
            Zs[b][1] = ev[b][1] + ev[b][3];
        }
#pragma unroll
        for (int msk = 4; msk <= 16; msk <<= 1)
#pragma unroll
            for (int b = 0; b < 2; ++b)
#pragma unroll
                for (int e = 0; e < 2; ++e)
                    Zs[b][e] += __shfl_xor_sync(0xffffffffu, Zs[b][e], msk);

        // exp weights transposed to wtb[o][n]
#pragma unroll
        for (int b = 0; b < 2; ++b)
#pragma unroll
            for (int q = 0; q < 4; ++q)
                wtb[(w * 16 + 2 * tig + (q & 1) + 8 * b) * 20 + gid + 8 * (q >> 1)] = ev[b][q];

        // unnormalized Z for this lane's column
        const int zsrc = (lane & 7) >> 1;
        float z00 = __shfl_sync(0xffffffffu, Zs[0][0], zsrc);
        float z01 = __shfl_sync(0xffffffffu, Zs[0][1], zsrc);
        float z10 = __shfl_sync(0xffffffffu, Zs[1][0], zsrc);
        float z11 = __shfl_sync(0xffffffffu, Zs[1][1], zsrc);
        float ze0 = (lane & 1) ? z01 : z00;
        float ze1 = (lane & 1) ? z11 : z10;
        float Zm  = (lane & 8) ? ze1 : ze0;
        float invZ = __frcp_rn(Zm);
        __syncwarp();

        // ------------- V accumulation from fp16 ring + tt fold -------------
        float Acc[4] = {0.f, 0.f, 0.f, 0.f};
        float st0 = 0.f, st1 = 0.f, st2 = 0.f;
#pragma unroll
        for (int h = 0; h < 4; ++h) {
            float4 wq4 = *(const float4*)&wtb[(w * 16 + o) * 20 + 4 * h];
#pragma unroll
            for (int j = 0; j < 4; ++j) {
                int n = 4 * h + j;
                float wn = (j == 0) ? wq4.x : (j == 1) ? wq4.y : (j == 2) ? wq4.z : wq4.w;
                ull vv = vrp[(n * 4 + w) * 32 + lane];
                unsigned vlo = (unsigned)vv, vhi = (unsigned)(vv >> 32);
                float2 f0 = __half22float2(*(const __half2*)&vlo);
                float2 f1 = __half22float2(*(const __half2*)&vhi);
                float4 t4 = ttb[w * 16 + n];
                Acc[0] = fmaf(wn, f0.x, Acc[0]);
                Acc[1] = fmaf(wn, f0.y, Acc[1]);
                Acc[2] = fmaf(wn, f1.x, Acc[2]);
                Acc[3] = fmaf(wn, f1.y, Acc[3]);
                st0 = fmaf(wn, t4.x, st0);
                st1 = fmaf(wn, t4.y, st1);
                st2 = fmaf(wn, t4.z, st2);
            }
        }

#pragma unroll
        for (int r = 0; r < 4; ++r) {
            float pesum = fmaf(pw2v[r][2], st2,
                          fmaf(pw2v[r][1], st1,
                          fmaf(pw2v[r][0], st0, pb2v[r] * Zm)));
            out[(size_t)i * CH + lane + 32 * r] = (Acc[r] + pesum) * invZ;
        }
    }
}

// ---------------------------------------------------------------------------
extern "C" void kernel_launch(void* const* d_in, const int* in_sizes, int n_in,
                              void* d_out, int out_size)
{
    const float* p    = (const float*)d_in[0];
    const float* x    = (const float*)d_in[1];
    const int*   idx  = (const int*)  d_in[2];
    const float* wq   = (const float*)d_in[3];
    const float* bq   = (const float*)d_in[4];
    const float* wk   = (const float*)d_in[5];
    const float* bk   = (const float*)d_in[6];
    const float* wv   = (const float*)d_in[7];
    const float* bv   = (const float*)d_in[8];
    const float* pw1  = (const float*)d_in[9];
    const float* pb1  = (const float*)d_in[10];
    const float* pbng = (const float*)d_in[11];
    const float* pbnb = (const float*)d_in[12];
    const float* pbnm = (const float*)d_in[13];
    const float* pbnv = (const float*)d_in[14];
    const float* pw2  = (const float*)d_in[15];
    const float* pb2  = (const float*)d_in[16];
    const float* bn1g = (const float*)d_in[17];
    const float* bn1b = (const float*)d_in[18];
    const float* bn1m = (const float*)d_in[19];
    const float* bn1v = (const float*)d_in[20];
    const float* ww1  = (const float*)d_in[21];
    const float* wb1  = (const float*)d_in[22];
    const float* bn2g = (const float*)d_in[23];
    const float* bn2b = (const float*)d_in[24];
    const float* bn2m = (const float*)d_in[25];
    const float* bn2v = (const float*)d_in[26];
    const float* ww2  = (const float*)d_in[27];
    const float* wb2  = (const float*)d_in[28];
    float* out = (float*)d_out;

    cudaFuncSetAttribute(attn_kernel,
                         cudaFuncAttributeMaxDynamicSharedMemorySize, SMEM_ATTN);

    prep_kernel<<<NPTS / 256, 256>>>(p);
    qkv_tc_kernel<<<dim3(NPTS / 128, 3), 256>>>(x, wq, bq, wk, bk, wv, bv);

    attn_kernel<<<NPTS / (PPW * 4), 128, SMEM_ATTN>>>(
        idx,
        pw1, pb1, pbng, pbnb, pbnm, pbnv, pw2, pb2,
        bn1g, bn1b, bn1m, bn1v, ww1, wb1,
        bn2g, bn2b, bn2m, bn2v, ww2, wb2,
        out);
}

// round 15
// speedup vs baseline: 1.0891x; 1.0148x over previous
#include <cuda_runtime.h>
#include <cuda_fp16.h>
#include <math.h>

#define NPTS 65536
#define NS   16
#define CH   128
#define EPSB 1e-5f
#define LOG2E 1.4426950408889634f

typedef unsigned long long ull;

__device__ __forceinline__ void cpasync8(unsigned dst, const void* src) {
    asm volatile("cp.async.ca.shared.global [%0],[%1],8;" :: "r"(dst), "l"(src));
}
__device__ __forceinline__ void cpcommit() {
    asm volatile("cp.async.commit_group;");
}
template<int N> __device__ __forceinline__ void cpwaitg() {
    asm volatile("cp.async.wait_group %0;" :: "n"(N));
}
__device__ __forceinline__ unsigned f2tf32(float f) {
    unsigned u; asm("cvt.rna.tf32.f32 %0,%1;" : "=r"(u) : "f"(f)); return u;
}
__device__ __forceinline__ unsigned bf16x2hl(float hi, float lo) {
    unsigned d; asm("cvt.rn.bf16x2.f32 %0,%1,%2;" : "=r"(d) : "f"(hi), "f"(lo)); return d;
}
__device__ __forceinline__ unsigned f16x2hl(float hi, float lo) {
    unsigned d; asm("cvt.rn.f16x2.f32 %0,%1,%2;" : "=r"(d) : "f"(hi), "f"(lo)); return d;
}
__device__ __forceinline__ float bflo(unsigned u) {
    return __uint_as_float(u << 16);
}
__device__ __forceinline__ float bfhi(unsigned u) {
    return __uint_as_float(u & 0xffff0000u);
}
__device__ __forceinline__ void mma_tf32(float c[4],
                                         unsigned a0, unsigned a1,
                                         unsigned a2, unsigned a3,
                                         unsigned b0, unsigned b1) {
    asm("mma.sync.aligned.m16n8k8.row.col.f32.tf32.tf32.f32 "
        "{%0,%1,%2,%3},{%4,%5,%6,%7},{%8,%9},{%0,%1,%2,%3};"
        : "+f"(c[0]), "+f"(c[1]), "+f"(c[2]), "+f"(c[3])
        : "r"(a0), "r"(a1), "r"(a2), "r"(a3), "r"(b0), "r"(b1));
}
__device__ __forceinline__ void mma_bf16(float c[4],
                                         unsigned a0, unsigned a1,
                                         unsigned a2, unsigned a3,
                                         unsigned b0, unsigned b1) {
    asm("mma.sync.aligned.m16n8k16.row.col.f32.bf16.bf16.f32 "
        "{%0,%1,%2,%3},{%4,%5,%6,%7},{%8,%9},{%0,%1,%2,%3};"
        : "+f"(c[0]), "+f"(c[1]), "+f"(c[2]), "+f"(c[3])
        : "r"(a0), "r"(a1), "r"(a2), "r"(a3), "r"(b0), "r"(b1));
}

// static device scratch (allocation-guard safe)
__device__ float  g_q [(size_t)NPTS * CH];
__device__ ull    g_kb[(size_t)NPTS * 32];   // bf16 K packed: 256B/point
__device__ ull    g_vh[(size_t)NPTS * 32];   // fp16 V packed: 256B/point
__device__ float4 g_p4[NPTS];

// ---------------------------------------------------------------------------
// Kernel 1: QKV GEMM on tensor cores (R12-exact mainloop).
// grid (512, 4): y<3 -> q/k/v GEMM; y==3 -> position packing (prep folded in).
// ---------------------------------------------------------------------------
__global__ void __launch_bounds__(256)
qkv_tc_kernel(const float* __restrict__ x, const float* __restrict__ p,
              const float* __restrict__ wq, const float* __restrict__ bq,
              const float* __restrict__ wk, const float* __restrict__ bk,
              const float* __restrict__ wv, const float* __restrict__ bv)
{
    __shared__ unsigned Xs[128][36];
    __shared__ unsigned Ws[128][36];

    const int sel = blockIdx.y;
    if (sel == 3) {
        // folded prep: pack positions into float4 (128 points per block)
        int i = blockIdx.x * 128 + (threadIdx.x & 127);
        if (threadIdx.x < 128)
            g_p4[i] = make_float4(p[3 * i + 0], p[3 * i + 1], p[3 * i + 2], 0.f);
        return;
    }

    const float* W;
    const float* bias;
    if (sel == 0)      { W = wq; bias = bq; }
    else if (sel == 1) { W = wk; bias = bk; }
    else               { W = wv; bias = bv; }

    const int tid  = threadIdx.x;
    const int warp = tid >> 5;
    const int lane = tid & 31;
    const int gid  = lane >> 2;
    const int tig  = lane & 3;
    const int m0   = blockIdx.x * 128;
    const int r0   = warp * 16;

    const int srow = tid >> 1;
    const int skq  = (tid & 1) * 16;

    float c[16][4];
#pragma unroll
    for (int nb = 0; nb < 16; ++nb)
#pragma unroll
        for (int j = 0; j < 4; ++j) c[nb][j] = 0.f;

#pragma unroll 1
    for (int ch = 0; ch < 4; ++ch) {
#pragma unroll
        for (int i = 0; i < 4; ++i) {
            float4 xv = *(const float4*)&x[(size_t)(m0 + srow) * 128 + ch * 32 + skq + 4 * i];
            float4 wv = *(const float4*)&W[(size_t)srow * 128 + ch * 32 + skq + 4 * i];
            uint4 xt, wt;
            xt.x = f2tf32(xv.x); xt.y = f2tf32(xv.y); xt.z = f2tf32(xv.z); xt.w = f2tf32(xv.w);
            wt.x = f2tf32(wv.x); wt.y = f2tf32(wv.y); wt.z = f2tf32(wv.z); wt.w = f2tf32(wv.w);
            *(uint4*)&Xs[srow][skq + 4 * i] = xt;
            *(uint4*)&Ws[srow][skq + 4 * i] = wt;
        }
        __syncthreads();

#pragma unroll
        for (int ks = 0; ks < 4; ++ks) {
            const int k = ks * 8;
            unsigned a0 = Xs[r0 + gid][k + tig];
            unsigned a1 = Xs[r0 + gid + 8][k + tig];
            unsigned a2 = Xs[r0 + gid][k + tig + 4];
            unsigned a3 = Xs[r0 + gid + 8][k + tig + 4];
#pragma unroll
            for (int nb = 0; nb < 16; ++nb) {
                unsigned b0 = Ws[nb * 8 + gid][k + tig];
                unsigned b1 = Ws[nb * 8 + gid][k + tig + 4];
                mma_tf32(c[nb], a0, a1, a2, a3, b0, b1);
            }
        }
        __syncthreads();
    }

    if (sel == 0) {
#pragma unroll
        for (int nb = 0; nb < 16; ++nb) {
            const int col = nb * 8 + 2 * tig;
            const float2 bv = *(const float2*)&bias[col];
            const size_t row = (size_t)(m0 + r0 + gid);
            *(float2*)&g_q[row * 128 + col] =
                make_float2(c[nb][0] + bv.x, c[nb][1] + bv.y);
            *(float2*)&g_q[(row + 8) * 128 + col] =
                make_float2(c[nb][2] + bv.x, c[nb][3] + bv.y);
        }
    } else if (sel == 1) {
        // K: bf16 packed per lane-slot l: {(k(l),k(l+32)),(k(l+64),k(l+96))}
#pragma unroll
        for (int nb = 0; nb < 4; ++nb)
#pragma unroll
            for (int e = 0; e < 2; ++e) {
                const int l = nb * 8 + 2 * tig + e;
                const float b0 = bias[l], b1 = bias[l + 32];
                const float b2 = bias[l + 64], b3 = bias[l + 96];
                unsigned lo = bf16x2hl(c[nb + 4][e] + b1, c[nb][e] + b0);
                unsigned hi = bf16x2hl(c[nb + 12][e] + b3, c[nb + 8][e] + b2);
                g_kb[(size_t)(m0 + r0 + gid) * 32 + l] = ((ull)hi << 32) | lo;
                unsigned lo2 = bf16x2hl(c[nb + 4][e + 2] + b1, c[nb][e + 2] + b0);
                unsigned hi2 = bf16x2hl(c[nb + 12][e + 2] + b3, c[nb + 8][e + 2] + b2);
                g_kb[(size_t)(m0 + r0 + gid + 8) * 32 + l] = ((ull)hi2 << 32) | lo2;
            }
    } else {
        // V: fp16 packed, same layout as K (single rounding)
#pragma unroll
        for (int nb = 0; nb < 4; ++nb)
#pragma unroll
            for (int e = 0; e < 2; ++e) {
                const int l = nb * 8 + 2 * tig + e;
                const float b0 = bias[l], b1 = bias[l + 32];
                const float b2 = bias[l + 64], b3 = bias[l + 96];
                unsigned lo = f16x2hl(c[nb + 4][e] + b1, c[nb][e] + b0);
                unsigned hi = f16x2hl(c[nb + 12][e] + b3, c[nb + 8][e] + b2);
                g_vh[(size_t)(m0 + r0 + gid) * 32 + l] = ((ull)hi << 32) | lo;
                unsigned lo2 = f16x2hl(c[nb + 4][e + 2] + b1, c[nb][e + 2] + b0);
                unsigned hi2 = f16x2hl(c[nb + 12][e + 2] + b3, c[nb + 8][e + 2] + b2);
                g_vh[(size_t)(m0 + r0 + gid + 8) * 32 + l] = ((ull)hi2 << 32) | lo2;
            }
    }
}

// ---------------------------------------------------------------------------
// Kernel 2: tensor-core attention (R14-exact).
// ---------------------------------------------------------------------------
#define PPW 8
// smem offsets (bytes)
#define OFF_KR  0        // ull [16][4][32]       = 16384
#define OFF_VR  16384    // ull [16][4][32]       = 16384
#define OFF_WSM 32768    // unsigned [4][16][68]  = 17408
#define OFF_TT  50176    // float4 [4][16]        = 1024
#define OFF_WT  51200    // float [4][16][20]     = 5120
#define SMEM_ATTN 56320

__global__ void __launch_bounds__(128, 4)
attn_kernel(const int* __restrict__ idx,
            const float* __restrict__ pw1, const float* __restrict__ pb1,
            const float* __restrict__ pbng, const float* __restrict__ pbnb,
            const float* __restrict__ pbnm, const float* __restrict__ pbnv,
            const float* __restrict__ pw2, const float* __restrict__ pb2,
            const float* __restrict__ bn1g, const float* __restrict__ bn1b,
            const float* __restrict__ bn1m, const float* __restrict__ bn1v,
            const float* __restrict__ ww1, const float* __restrict__ wb1,
            const float* __restrict__ bn2g, const float* __restrict__ bn2b,
            const float* __restrict__ bn2m, const float* __restrict__ bn2v,
            const float* __restrict__ ww2, const float* __restrict__ wb2,
            float* __restrict__ out)
{
    extern __shared__ char dsm[];
    ull*      krp = (ull*)(dsm + OFF_KR);
    ull*      vrp = (ull*)(dsm + OFF_VR);
    unsigned* wsm = (unsigned*)(dsm + OFF_WSM);
    float4*   ttb = (float4*)(dsm + OFF_TT);
    float*    wtb = (float*)(dsm + OFF_WT);

    const int lane = threadIdx.x & 31;
    const int w    = (threadIdx.x >> 5) & 3;
    const int gw   = blockIdx.x * (blockDim.x >> 5) + (threadIdx.x >> 5);
    const int gid  = lane >> 2;
    const int tig  = lane & 3;
    const int o    = lane & 15;

    // W1 bf16 B-fragments (R9-proven mapping)
    unsigned bw1[8][2][2];
#pragma unroll
    for (int s = 0; s < 8; ++s)
#pragma unroll
        for (int b = 0; b < 2; ++b)
#pragma unroll
            for (int j = 0; j < 2; ++j) {
                int pp = 8 * s + tig + 4 * j;
                int c = (pp < 32) ? pp : pp + 32;
                int oo = 8 * b + gid;
                bw1[s][b][j] = bf16x2hl(ww1[oo * CH + c + 32], ww1[oo * CH + c]);
            }

    // W2 tf32 B-fragments (LOG2E folded)
    unsigned w2f[2][2][2];
#pragma unroll
    for (int s = 0; s < 2; ++s)
#pragma unroll
        for (int b = 0; b < 2; ++b)
#pragma unroll
            for (int j = 0; j < 2; ++j) {
                int u = 8 * s + tig + 4 * j;
                int oo = 8 * b + gid;
                w2f[s][b][j] = f2tf32(ww2[oo * 16 + u] * LOG2E);
            }

    // BN2 constants on c-frag cols
    float s2c[4], b2c[4];
#pragma unroll
    for (int j = 0; j < 4; ++j) {
        int u = 2 * tig + (j & 1) + 8 * (j >> 1);
        float s = bn2g[u] * rsqrtf(bn2v[u] + EPSB);
        s2c[j] = s;
        b2c[j] = bn2b[u] - bn2m[u] * s + wb1[u] * s;
    }

    float s1[4], b1f[4], pw2v[4][3], pb2v[4];
#pragma unroll
    for (int r = 0; r < 4; ++r) {
        int c = lane + 32 * r;
        float s = bn1g[c] * rsqrtf(bn1v[c] + EPSB);
        s1[r]  = s;
        b1f[r] = bn1b[c] - bn1m[c] * s;
        pw2v[r][0] = pw2[c * 3 + 0];
        pw2v[r][1] = pw2[c * 3 + 1];
        pw2v[r][2] = pw2[c * 3 + 2];
        pb2v[r] = pb2[c];
    }
    float Af[9], df[3];
#pragma unroll
    for (int a = 0; a < 3; ++a) {
        float s  = pbng[a] * rsqrtf(pbnv[a] + EPSB);
        float sh = pbnb[a] - pbnm[a] * s;
#pragma unroll
        for (int b = 0; b < 3; ++b) Af[a * 3 + b] = s * pw1[a * 3 + b];
        df[a] = s * pb1[a] + sh;
    }

    const unsigned kr0 =
        (unsigned)__cvta_generic_to_shared(&krp[w * 32 + lane]);
    const unsigned vr0 =
        (unsigned)__cvta_generic_to_shared(&vrp[w * 32 + lane]);

#pragma unroll 1
    for (int t = 0; t < PPW; ++t) {
        const int i = gw * PPW + t;

        const float4 pi = g_p4[i];
        float xqf[4];
#pragma unroll
        for (int r = 0; r < 4; ++r) {
            float xq = g_q[(size_t)i * CH + lane + 32 * r];
            xqf[r] = b1f[r] - s1[r] * xq;
        }
        const int myj = idx[i * NS + o];
        const float4 pjall = g_p4[myj];

        // issue all 16 neighbors' K+V loads (4 commit groups of 4 neighbors)
#pragma unroll
        for (int g = 0; g < 4; ++g) {
#pragma unroll
            for (int e = 0; e < 4; ++e) {
                int n = 4 * g + e;
                int js = __shfl_sync(0xffffffffu, myj, n);
                cpasync8(kr0 + (unsigned)n * 1024u, &g_kb[(size_t)js * 32 + lane]);
                cpasync8(vr0 + (unsigned)n * 1024u, &g_vh[(size_t)js * 32 + lane]);
            }
            cpcommit();
        }

        // ---------------- Phase 1: consume K, build wsm + ttb ----------------
        auto body = [&](int n) {
            ull kk = krp[(n * 4 + w) * 32 + lane];
            unsigned klo = (unsigned)kk, khi = (unsigned)(kk >> 32);
            float gk[4] = {bflo(klo), bfhi(klo), bflo(khi), bfhi(khi)};
            float pr0 = __shfl_sync(0xffffffffu, pjall.x, n) - pi.x;
            float pr1 = __shfl_sync(0xffffffffu, pjall.y, n) - pi.y;
            float pr2 = __shfl_sync(0xffffffffu, pjall.z, n) - pi.z;

            float tt[3];
#pragma unroll
            for (int a = 0; a < 3; ++a) {
                float v = fmaf(pr2, Af[a * 3 + 2],
                          fmaf(pr1, Af[a * 3 + 1],
                          fmaf(pr0, Af[a * 3 + 0], df[a])));
                tt[a] = fmaxf(v, 0.f);
            }
            if (lane == 0)
                ttb[w * 16 + n] = make_float4(tt[0], tt[1], tt[2], 0.f);

            float wp[4];
#pragma unroll
            for (int r = 0; r < 4; ++r) {
                float pe = fmaf(tt[2], pw2v[r][2],
                           fmaf(tt[1], pw2v[r][1],
                           fmaf(tt[0], pw2v[r][0], pb2v[r])));
                wp[r] = fmaxf(fmaf(gk[r] + pe, s1[r], xqf[r]), 0.f);
            }
            wsm[(w * 16 + n) * 68 + lane]      = bf16x2hl(wp[1], wp[0]);
            wsm[(w * 16 + n) * 68 + 32 + lane] = bf16x2hl(wp[3], wp[2]);
        };
        cpwaitg<3>(); body(0);  body(1);  body(2);  body(3);
        cpwaitg<2>(); body(4);  body(5);  body(6);  body(7);
        cpwaitg<1>(); body(8);  body(9);  body(10); body(11);
        cpwaitg<0>(); body(12); body(13); body(14); body(15);
        __syncwarp();

        // ---------------- Phase 2: tensor-core logits ----------------
        float c1[2][4] = {{0.f, 0.f, 0.f, 0.f}, {0.f, 0.f, 0.f, 0.f}};
#pragma unroll
        for (int s = 0; s < 8; ++s) {
            unsigned a0 = wsm[(w * 16 + gid)     * 68 + 8 * s + tig];
            unsigned a1 = wsm[(w * 16 + gid + 8) * 68 + 8 * s + tig];
            unsigned a2 = wsm[(w * 16 + gid)     * 68 + 8 * s + tig + 4];
            unsigned a3 = wsm[(w * 16 + gid + 8) * 68 + 8 * s + tig + 4];
            mma_bf16(c1[0], a0, a1, a2, a3, bw1[s][0][0], bw1[s][0][1]);
            mma_bf16(c1[1], a0, a1, a2, a3, bw1[s][1][0], bw1[s][1][1]);
        }

        // BN2 + ReLU
        float t1[2][4];
#pragma unroll
        for (int b = 0; b < 2; ++b)
#pragma unroll
            for (int q = 0; q < 4; ++q)
                t1[b][q] = fmaxf(fmaf(c1[b][q], s2c[(q & 1) + 2 * b],
                                      b2c[(q & 1) + 2 * b]), 0.f);

        // permute c-frag -> A-frag for GEMV2
        const int srcA = 4 * gid + (tig >> 1);
        const bool oddt = (tig & 1);
        unsigned aa[2][4];
#pragma unroll
        for (int s = 0; s < 2; ++s) {
            float v0 = __shfl_sync(0xffffffffu, t1[s][0], srcA);
            float v1 = __shfl_sync(0xffffffffu, t1[s][1], srcA);
            float v2 = __shfl_sync(0xffffffffu, t1[s][2], srcA);
            float v3 = __shfl_sync(0xffffffffu, t1[s][3], srcA);
            float u0v = oddt ? v1 : v0;
            float u1v = oddt ? v3 : v2;
            float q0 = __shfl_sync(0xffffffffu, t1[s][0], srcA + 2);
            float q1 = __shfl_sync(0xffffffffu, t1[s][1], srcA + 2);
            float q2 = __shfl_sync(0xffffffffu, t1[s][2], srcA + 2);
            float q3 = __shfl_sync(0xffffffffu, t1[s][3], srcA + 2);
            float u2v = oddt ? q1 : q0;
            float u3v = oddt ? q3 : q2;
            aa[s][0] = f2tf32(u0v); aa[s][1] = f2tf32(u1v);
            aa[s][2] = f2tf32(u2v); aa[s][3] = f2tf32(u3v);
        }

        float c2[2][4] = {{0.f, 0.f, 0.f, 0.f}, {0.f, 0.f, 0.f, 0.f}};
#pragma unroll
        for (int s = 0; s < 2; ++s) {
            mma_tf32(c2[0], aa[s][0], aa[s][1], aa[s][2], aa[s][3],
                     w2f[s][0][0], w2f[s][0][1]);
            mma_tf32(c2[1], aa[s][0], aa[s][1], aa[s][2], aa[s][3],
                     w2f[s][1][0], w2f[s][1][1]);
        }

        // softmax over neighbors (fragment rows)
        float mx[2][2], Zs[2][2];
#pragma unroll
        for (int b = 0; b < 2; ++b) {
            mx[b][0] = fmaxf(c2[b][0], c2[b][2]);
            mx[b][1] = fmaxf(c2[b][1], c2[b][3]);
        }
#pragma unroll
        for (int msk = 4; msk <= 16; msk <<= 1)
#pragma unroll
            for (int b = 0; b < 2; ++b)
#pragma unroll
                for (int e = 0; e < 2; ++e)
                    mx[b][e] = fmaxf(mx[b][e],
                                     __shfl_xor_sync(0xffffffffu, mx[b][e], msk));
        float ev[2][4];
#pragma unroll
        for (int b = 0; b < 2; ++b)
#pragma unroll
            for (int q = 0; q < 4; ++q)
                ev[b][q] = exp2f(c2[b][q] - mx[b][q & 1]);
#pragma unroll
        for (int b = 0; b < 2; ++b) {
            Zs[b][0] = ev[b][0] + ev[b][2];
            Zs[b][1] = ev[b][1] + ev[b][3];
        }
#pragma unroll
        for (int msk = 4; msk <= 16; msk <<= 1)
#pragma unroll
            for (int b = 0; b < 2; ++b)
#pragma unroll
                for (int e = 0; e < 2; ++e)
                    Zs[b][e] += __shfl_xor_sync(0xffffffffu, Zs[b][e], msk);

        // exp weights transposed to wtb[o][n]
#pragma unroll
        for (int b = 0; b < 2; ++b)
#pragma unroll
            for (int q = 0; q < 4; ++q)
                wtb[(w * 16 + 2 * tig + (q & 1) + 8 * b) * 20 + gid + 8 * (q >> 1)] = ev[b][q];

        // unnormalized Z for this lane's column
        const int zsrc = (lane & 7) >> 1;
        float z00 = __shfl_sync(0xffffffffu, Zs[0][0], zsrc);
        float z01 = __shfl_sync(0xffffffffu, Zs[0][1], zsrc);
        float z10 = __shfl_sync(0xffffffffu, Zs[1][0], zsrc);
        float z11 = __shfl_sync(0xffffffffu, Zs[1][1], zsrc);
        float ze0 = (lane & 1) ? z01 : z00;
        float ze1 = (lane & 1) ? z11 : z10;
        float Zm  = (lane & 8) ? ze1 : ze0;
        float invZ = __frcp_rn(Zm);
        __syncwarp();

        // ------------- V accumulation from fp16 ring + tt fold -------------
        float Acc[4] = {0.f, 0.f, 0.f, 0.f};
        float st0 = 0.f, st1 = 0.f, st2 = 0.f;
#pragma unroll
        for (int h = 0; h < 4; ++h) {
            float4 wq4 = *(const float4*)&wtb[(w * 16 + o) * 20 + 4 * h];
#pragma unroll
            for (int j = 0; j < 4; ++j) {
                int n = 4 * h + j;
                float wn = (j == 0) ? wq4.x : (j == 1) ? wq4.y : (j == 2) ? wq4.z : wq4.w;
                ull vv = vrp[(n * 4 + w) * 32 + lane];
                unsigned vlo = (unsigned)vv, vhi = (unsigned)(vv >> 32);
                float2 f0 = __half22float2(*(const __half2*)&vlo);
                float2 f1 = __half22float2(*(const __half2*)&vhi);
                float4 t4 = ttb[w * 16 + n];
                Acc[0] = fmaf(wn, f0.x, Acc[0]);
                Acc[1] = fmaf(wn, f0.y, Acc[1]);
                Acc[2] = fmaf(wn, f1.x, Acc[2]);
                Acc[3] = fmaf(wn, f1.y, Acc[3]);
                st0 = fmaf(wn, t4.x, st0);
                st1 = fmaf(wn, t4.y, st1);
                st2 = fmaf(wn, t4.z, st2);
            }
        }

#pragma unroll
        for (int r = 0; r < 4; ++r) {
            float pesum = fmaf(pw2v[r][2], st2,
                          fmaf(pw2v[r][1], st1,
                          fmaf(pw2v[r][0], st0, pb2v[r] * Zm)));
            out[(size_t)i * CH + lane + 32 * r] = (Acc[r] + pesum) * invZ;
        }
    }
}

// ---------------------------------------------------------------------------
extern "C" void kernel_launch(void* const* d_in, const int* in_sizes, int n_in,
                              void* d_out, int out_size)
{
    const float* p    = (const float*)d_in[0];
    const float* x    = (const float*)d_in[1];
    const int*   idx  = (const int*)  d_in[2];
    const float* wq   = (const float*)d_in[3];
    const float* bq   = (const float*)d_in[4];
    const float* wk   = (const float*)d_in[5];
    const float* bk   = (const float*)d_in[6];
    const float* wv   = (const float*)d_in[7];
    const float* bv   = (const float*)d_in[8];
    const float* pw1  = (const float*)d_in[9];
    const float* pb1  = (const float*)d_in[10];
    const float* pbng = (const float*)d_in[11];
    const float* pbnb = (const float*)d_in[12];
    const float* pbnm = (const float*)d_in[13];
    const float* pbnv = (const float*)d_in[14];
    const float* pw2  = (const float*)d_in[15];
    const float* pb2  = (const float*)d_in[16];
    const float* bn1g = (const float*)d_in[17];
    const float* bn1b = (const float*)d_in[18];
    const float* bn1m = (const float*)d_in[19];
    const float* bn1v = (const float*)d_in[20];
    const float* ww1  = (const float*)d_in[21];
    const float* wb1  = (const float*)d_in[22];
    const float* bn2g = (const float*)d_in[23];
    const float* bn2b = (const float*)d_in[24];
    const float* bn2m = (const float*)d_in[25];
    const float* bn2v = (const float*)d_in[26];
    const float* ww2  = (const float*)d_in[27];
    const float* wb2  = (const float*)d_in[28];
    float* out = (float*)d_out;

    cudaFuncSetAttribute(attn_kernel,
                         cudaFuncAttributeMaxDynamicSharedMemorySize, SMEM_ATTN);

    qkv_tc_kernel<<<dim3(NPTS / 128, 4), 256>>>(x, p, wq, bq, wk, bk, wv, bv);

    attn_kernel<<<NPTS / (PPW * 4), 128, SMEM_ATTN>>>(
        idx,
        pw1, pb1, pbng, pbnb, pbnm, pbnv, pw2, pb2,
        bn1g, bn1b, bn1m, bn1v, ww1, wb1,
        bn2g, bn2b, bn2m, bn2v, ww2, wb2,
        out);
}

// round 16
// speedup vs baseline: 1.1451x; 1.0514x over previous
#include <cuda_runtime.h>
#include <cuda_fp16.h>
#include <math.h>

#define NPTS 65536
#define NS   16
#define CH   128
#define EPSB 1e-5f
#define LOG2E 1.4426950408889634f

typedef unsigned long long ull;

__device__ __forceinline__ void cpasync8(unsigned dst, const void* src) {
    asm volatile("cp.async.ca.shared.global [%0],[%1],8;" :: "r"(dst), "l"(src));
}
__device__ __forceinline__ void cpcommit() {
    asm volatile("cp.async.commit_group;");
}
template<int N> __device__ __forceinline__ void cpwaitg() {
    asm volatile("cp.async.wait_group %0;" :: "n"(N));
}
__device__ __forceinline__ unsigned f2tf32(float f) {
    unsigned u; asm("cvt.rna.tf32.f32 %0,%1;" : "=r"(u) : "f"(f)); return u;
}
__device__ __forceinline__ unsigned bf16x2hl(float hi, float lo) {
    unsigned d; asm("cvt.rn.bf16x2.f32 %0,%1,%2;" : "=r"(d) : "f"(hi), "f"(lo)); return d;
}
__device__ __forceinline__ unsigned f16x2hl(float hi, float lo) {
    unsigned d; asm("cvt.rn.f16x2.f32 %0,%1,%2;" : "=r"(d) : "f"(hi), "f"(lo)); return d;
}
__device__ __forceinline__ float bflo(unsigned u) {
    return __uint_as_float(u << 16);
}
__device__ __forceinline__ float bfhi(unsigned u) {
    return __uint_as_float(u & 0xffff0000u);
}
__device__ __forceinline__ void mma_tf32(float c[4],
                                         unsigned a0, unsigned a1,
                                         unsigned a2, unsigned a3,
                                         unsigned b0, unsigned b1) {
    asm("mma.sync.aligned.m16n8k8.row.col.f32.tf32.tf32.f32 "
        "{%0,%1,%2,%3},{%4,%5,%6,%7},{%8,%9},{%0,%1,%2,%3};"
        : "+f"(c[0]), "+f"(c[1]), "+f"(c[2]), "+f"(c[3])
        : "r"(a0), "r"(a1), "r"(a2), "r"(a3), "r"(b0), "r"(b1));
}
__device__ __forceinline__ void mma_f16(float c[4],
                                        unsigned a0, unsigned a1,
                                        unsigned a2, unsigned a3,
                                        unsigned b0, unsigned b1) {
    asm("mma.sync.aligned.m16n8k16.row.col.f32.f16.f16.f32 "
        "{%0,%1,%2,%3},{%4,%5,%6,%7},{%8,%9},{%0,%1,%2,%3};"
        : "+f"(c[0]), "+f"(c[1]), "+f"(c[2]), "+f"(c[3])
        : "r"(a0), "r"(a1), "r"(a2), "r"(a3), "r"(b0), "r"(b1));
}
__device__ __forceinline__ void mma_bf16(float c[4],
                                         unsigned a0, unsigned a1,
                                         unsigned a2, unsigned a3,
                                         unsigned b0, unsigned b1) {
    asm("mma.sync.aligned.m16n8k16.row.col.f32.bf16.bf16.f32 "
        "{%0,%1,%2,%3},{%4,%5,%6,%7},{%8,%9},{%0,%1,%2,%3};"
        : "+f"(c[0]), "+f"(c[1]), "+f"(c[2]), "+f"(c[3])
        : "r"(a0), "r"(a1), "r"(a2), "r"(a3), "r"(b0), "r"(b1));
}

// static device scratch (allocation-guard safe)
__device__ float  g_q [(size_t)NPTS * CH];
__device__ ull    g_kb[(size_t)NPTS * 32];   // bf16 K packed: 256B/point
__device__ ull    g_vh[(size_t)NPTS * 32];   // fp16 V packed: 256B/point
__device__ float4 g_p4[NPTS];

// ---------------------------------------------------------------------------
// Kernel 1: QKV GEMM on fp16 tensor cores (mma.m16n8k16.f16, fp32 accum).
// K staged as f16x2 pairs: entry e holds (k=2e, 2e+1). Pad 20 -> conflict-free
// operand loads (bank = (20*gid + tig) mod 32, all distinct).
// grid (512, 4): y<3 -> q/k/v GEMM; y==3 -> position packing (prep folded in).
// ---------------------------------------------------------------------------
__global__ void __launch_bounds__(256)
qkv_tc_kernel(const float* __restrict__ x, const float* __restrict__ p,
              const float* __restrict__ wq, const float* __restrict__ bq,
              const float* __restrict__ wk, const float* __restrict__ bk,
              const float* __restrict__ wv, const float* __restrict__ bv)
{
    __shared__ unsigned Xh[128][20];
    __shared__ unsigned Wh[128][20];

    const int sel = blockIdx.y;
    if (sel == 3) {
        int i = blockIdx.x * 128 + (threadIdx.x & 127);
        if (threadIdx.x < 128)
            g_p4[i] = make_float4(p[3 * i + 0], p[3 * i + 1], p[3 * i + 2], 0.f);
        return;
    }

    const float* W;
    const float* bias;
    if (sel == 0)      { W = wq; bias = bq; }
    else if (sel == 1) { W = wk; bias = bk; }
    else               { W = wv; bias = bv; }

    const int tid  = threadIdx.x;
    const int warp = tid >> 5;
    const int lane = tid & 31;
    const int gid  = lane >> 2;
    const int tig  = lane & 3;
    const int m0   = blockIdx.x * 128;
    const int r0   = warp * 16;

    const int srow = tid >> 1;
    const int skq  = (tid & 1) * 16;       // k offset within 32-chunk
    const int p0   = (tid & 1) * 8;        // pair offset

    float c[16][4];
#pragma unroll
    for (int nb = 0; nb < 16; ++nb)
#pragma unroll
        for (int j = 0; j < 4; ++j) c[nb][j] = 0.f;

#pragma unroll 1
    for (int ch = 0; ch < 4; ++ch) {
        // stage chunk: 16 floats -> 8 f16x2 pairs, 2x STS.128 each
        {
            float xv[16], wv[16];
#pragma unroll
            for (int i = 0; i < 4; ++i) {
                float4 a = *(const float4*)&x[(size_t)(m0 + srow) * 128 + ch * 32 + skq + 4 * i];
                float4 b = *(const float4*)&W[(size_t)srow * 128 + ch * 32 + skq + 4 * i];
                xv[4 * i] = a.x; xv[4 * i + 1] = a.y; xv[4 * i + 2] = a.z; xv[4 * i + 3] = a.w;
                wv[4 * i] = b.x; wv[4 * i + 1] = b.y; wv[4 * i + 2] = b.z; wv[4 * i + 3] = b.w;
            }
            uint4 xo0, xo1, wo0, wo1;
            xo0.x = f16x2hl(xv[1],  xv[0]);  xo0.y = f16x2hl(xv[3],  xv[2]);
            xo0.z = f16x2hl(xv[5],  xv[4]);  xo0.w = f16x2hl(xv[7],  xv[6]);
            xo1.x = f16x2hl(xv[9],  xv[8]);  xo1.y = f16x2hl(xv[11], xv[10]);
            xo1.z = f16x2hl(xv[13], xv[12]); xo1.w = f16x2hl(xv[15], xv[14]);
            wo0.x = f16x2hl(wv[1],  wv[0]);  wo0.y = f16x2hl(wv[3],  wv[2]);
            wo0.z = f16x2hl(wv[5],  wv[4]);  wo0.w = f16x2hl(wv[7],  wv[6]);
            wo1.x = f16x2hl(wv[9],  wv[8]);  wo1.y = f16x2hl(wv[11], wv[10]);
            wo1.z = f16x2hl(wv[13], wv[12]); wo1.w = f16x2hl(wv[15], wv[14]);
            *(uint4*)&Xh[srow][p0]     = xo0;
            *(uint4*)&Xh[srow][p0 + 4] = xo1;
            *(uint4*)&Wh[srow][p0]     = wo0;
            *(uint4*)&Wh[srow][p0 + 4] = wo1;
        }
        __syncthreads();

        // two k=16 steps per 32-chunk
#pragma unroll
        for (int ks = 0; ks < 2; ++ks) {
            const int pb = 8 * ks;
            unsigned a0 = Xh[r0 + gid][pb + tig];
            unsigned a1 = Xh[r0 + gid + 8][pb + tig];
            unsigned a2 = Xh[r0 + gid][pb + tig + 4];
            unsigned a3 = Xh[r0 + gid + 8][pb + tig + 4];
#pragma unroll
            for (int nb = 0; nb < 16; ++nb) {
                unsigned b0 = Wh[nb * 8 + gid][pb + tig];
                unsigned b1 = Wh[nb * 8 + gid][pb + tig + 4];
                mma_f16(c[nb], a0, a1, a2, a3, b0, b1);
            }
        }
        __syncthreads();
    }

    if (sel == 0) {
#pragma unroll
        for (int nb = 0; nb < 16; ++nb) {
            const int col = nb * 8 + 2 * tig;
            const float2 bv = *(const float2*)&bias[col];
            const size_t row = (size_t)(m0 + r0 + gid);
            *(float2*)&g_q[row * 128 + col] =
                make_float2(c[nb][0] + bv.x, c[nb][1] + bv.y);
            *(float2*)&g_q[(row + 8) * 128 + col] =
                make_float2(c[nb][2] + bv.x, c[nb][3] + bv.y);
        }
    } else if (sel == 1) {
        // K: bf16 packed per lane-slot l: {(k(l),k(l+32)),(k(l+64),k(l+96))}
#pragma unroll
        for (int nb = 0; nb < 4; ++nb)
#pragma unroll
            for (int e = 0; e < 2; ++e) {
                const int l = nb * 8 + 2 * tig + e;
                const float b0 = bias[l], b1 = bias[l + 32];
                const float b2 = bias[l + 64], b3 = bias[l + 96];
                unsigned lo = bf16x2hl(c[nb + 4][e] + b1, c[nb][e] + b0);
                unsigned hi = bf16x2hl(c[nb + 12][e] + b3, c[nb + 8][e] + b2);
                g_kb[(size_t)(m0 + r0 + gid) * 32 + l] = ((ull)hi << 32) | lo;
                unsigned lo2 = bf16x2hl(c[nb + 4][e + 2] + b1, c[nb][e + 2] + b0);
                unsigned hi2 = bf16x2hl(c[nb + 12][e + 2] + b3, c[nb + 8][e + 2] + b2);
                g_kb[(size_t)(m0 + r0 + gid + 8) * 32 + l] = ((ull)hi2 << 32) | lo2;
            }
    } else {
        // V: fp16 packed, same layout as K
#pragma unroll
        for (int nb = 0; nb < 4; ++nb)
#pragma unroll
            for (int e = 0; e < 2; ++e) {
                const int l = nb * 8 + 2 * tig + e;
                const float b0 = bias[l], b1 = bias[l + 32];
                const float b2 = bias[l + 64], b3 = bias[l + 96];
                unsigned lo = f16x2hl(c[nb + 4][e] + b1, c[nb][e] + b0);
                unsigned hi = f16x2hl(c[nb + 12][e] + b3, c[nb + 8][e] + b2);
                g_vh[(size_t)(m0 + r0 + gid) * 32 + l] = ((ull)hi << 32) | lo;
                unsigned lo2 = f16x2hl(c[nb + 4][e + 2] + b1, c[nb][e + 2] + b0);
                unsigned hi2 = f16x2hl(c[nb + 12][e + 2] + b3, c[nb + 8][e + 2] + b2);
                g_vh[(size_t)(m0 + r0 + gid + 8) * 32 + l] = ((ull)hi2 << 32) | lo2;
            }
    }
}

// ---------------------------------------------------------------------------
// Kernel 2: tensor-core attention (R14/R15-exact).
// ---------------------------------------------------------------------------
#define PPW 8
// smem offsets (bytes)
#define OFF_KR  0        // ull [16][4][32]       = 16384
#define OFF_VR  16384    // ull [16][4][32]       = 16384
#define OFF_WSM 32768    // unsigned [4][16][68]  = 17408
#define OFF_TT  50176    // float4 [4][16]        = 1024
#define OFF_WT  51200    // float [4][16][20]     = 5120
#define SMEM_ATTN 56320

__global__ void __launch_bounds__(128, 4)
attn_kernel(const int* __restrict__ idx,
            const float* __restrict__ pw1, const float* __restrict__ pb1,
            const float* __restrict__ pbng, const float* __restrict__ pbnb,
            const float* __restrict__ pbnm, const float* __restrict__ pbnv,
            const float* __restrict__ pw2, const float* __restrict__ pb2,
            const float* __restrict__ bn1g, const float* __restrict__ bn1b,
            const float* __restrict__ bn1m, const float* __restrict__ bn1v,
            const float* __restrict__ ww1, const float* __restrict__ wb1,
            const float* __restrict__ bn2g, const float* __restrict__ bn2b,
            const float* __restrict__ bn2m, const float* __restrict__ bn2v,
            const float* __restrict__ ww2, const float* __restrict__ wb2,
            float* __restrict__ out)
{
    extern __shared__ char dsm[];
    ull*      krp = (ull*)(dsm + OFF_KR);
    ull*      vrp = (ull*)(dsm + OFF_VR);
    unsigned* wsm = (unsigned*)(dsm + OFF_WSM);
    float4*   ttb = (float4*)(dsm + OFF_TT);
    float*    wtb = (float*)(dsm + OFF_WT);

    const int lane = threadIdx.x & 31;
    const int w    = (threadIdx.x >> 5) & 3;
    const int gw   = blockIdx.x * (blockDim.x >> 5) + (threadIdx.x >> 5);
    const int gid  = lane >> 2;
    const int tig  = lane & 3;
    const int o    = lane & 15;

    // W1 bf16 B-fragments (R9-proven mapping)
    unsigned bw1[8][2][2];
#pragma unroll
    for (int s = 0; s < 8; ++s)
#pragma unroll
        for (int b = 0; b < 2; ++b)
#pragma unroll
            for (int j = 0; j < 2; ++j) {
                int pp = 8 * s + tig + 4 * j;
                int c = (pp < 32) ? pp : pp + 32;
                int oo = 8 * b + gid;
                bw1[s][b][j] = bf16x2hl(ww1[oo * CH + c + 32], ww1[oo * CH + c]);
            }

    // W2 tf32 B-fragments (LOG2E folded)
    unsigned w2f[2][2][2];
#pragma unroll
    for (int s = 0; s < 2; ++s)
#pragma unroll
        for (int b = 0; b < 2; ++b)
#pragma unroll
            for (int j = 0; j < 2; ++j) {
                int u = 8 * s + tig + 4 * j;
                int oo = 8 * b + gid;
                w2f[s][b][j] = f2tf32(ww2[oo * 16 + u] * LOG2E);
            }

    // BN2 constants on c-frag cols
    float s2c[4], b2c[4];
#pragma unroll
    for (int j = 0; j < 4; ++j) {
        int u = 2 * tig + (j & 1) + 8 * (j >> 1);
        float s = bn2g[u] * rsqrtf(bn2v[u] + EPSB);
        s2c[j] = s;
        b2c[j] = bn2b[u] - bn2m[u] * s + wb1[u] * s;
    }

    float s1[4], b1f[4], pw2v[4][3], pb2v[4];
#pragma unroll
    for (int r = 0; r < 4; ++r) {
        int c = lane + 32 * r;
        float s = bn1g[c] * rsqrtf(bn1v[c] + EPSB);
        s1[r]  = s;
        b1f[r] = bn1b[c] - bn1m[c] * s;
        pw2v[r][0] = pw2[c * 3 + 0];
        pw2v[r][1] = pw2[c * 3 + 1];
        pw2v[r][2] = pw2[c * 3 + 2];
        pb2v[r] = pb2[c];
    }
    float Af[9], df[3];
#pragma unroll
    for (int a = 0; a < 3; ++a) {
        float s  = pbng[a] * rsqrtf(pbnv[a] + EPSB);
        float sh = pbnb[a] - pbnm[a] * s;
#pragma unroll
        for (int b = 0; b < 3; ++b) Af[a * 3 + b] = s * pw1[a * 3 + b];
        df[a] = s * pb1[a] + sh;
    }

    const unsigned kr0 =
        (unsigned)__cvta_generic_to_shared(&krp[w * 32 + lane]);
    const unsigned vr0 =
        (unsigned)__cvta_generic_to_shared(&vrp[w * 32 + lane]);

#pragma unroll 1
    for (int t = 0; t < PPW; ++t) {
        const int i = gw * PPW + t;

        const float4 pi = g_p4[i];
        float xqf[4];
#pragma unroll
        for (int r = 0; r < 4; ++r) {
            float xq = g_q[(size_t)i * CH + lane + 32 * r];
            xqf[r] = b1f[r] - s1[r] * xq;
        }
        const int myj = idx[i * NS + o];
        const float4 pjall = g_p4[myj];

        // issue all 16 neighbors' K+V loads (4 commit groups of 4 neighbors)
#pragma unroll
        for (int g = 0; g < 4; ++g) {
#pragma unroll
            for (int e = 0; e < 4; ++e) {
                int n = 4 * g + e;
                int js = __shfl_sync(0xffffffffu, myj, n);
                cpasync8(kr0 + (unsigned)n * 1024u, &g_kb[(size_t)js * 32 + lane]);
                cpasync8(vr0 + (unsigned)n * 1024u, &g_vh[(size_t)js * 32 + lane]);
            }
            cpcommit();
        }

        // ---------------- Phase 1: consume K, build wsm + ttb ----------------
        auto body = [&](int n) {
            ull kk = krp[(n * 4 + w) * 32 + lane];
            unsigned klo = (unsigned)kk, khi = (unsigned)(kk >> 32);
            float gk[4] = {bflo(klo), bfhi(klo), bflo(khi), bfhi(khi)};
            float pr0 = __shfl_sync(0xffffffffu, pjall.x, n) - pi.x;
            float pr1 = __shfl_sync(0xffffffffu, pjall.y, n) - pi.y;
            float pr2 = __shfl_sync(0xffffffffu, pjall.z, n) - pi.z;

            float tt[3];
#pragma unroll
            for (int a = 0; a < 3; ++a) {
                float v = fmaf(pr2, Af[a * 3 + 2],
                          fmaf(pr1, Af[a * 3 + 1],
                          fmaf(pr0, Af[a * 3 + 0], df[a])));
                tt[a] = fmaxf(v, 0.f);
            }
            if (lane == 0)
                ttb[w * 16 + n] = make_float4(tt[0], tt[1], tt[2], 0.f);

            float wp[4];
#pragma unroll
            for (int r = 0; r < 4; ++r) {
                float pe = fmaf(tt[2], pw2v[r][2],
                           fmaf(tt[1], pw2v[r][1],
                           fmaf(tt[0], pw2v[r][0], pb2v[r])));
                wp[r] = fmaxf(fmaf(gk[r] + pe, s1[r], xqf[r]), 0.f);
            }
            wsm[(w * 16 + n) * 68 + lane]      = bf16x2hl(wp[1], wp[0]);
            wsm[(w * 16 + n) * 68 + 32 + lane] = bf16x2hl(wp[3], wp[2]);
        };
        cpwaitg<3>(); body(0);  body(1);  body(2);  body(3);
        cpwaitg<2>(); body(4);  body(5);  body(6);  body(7);
        cpwaitg<1>(); body(8);  body(9);  body(10); body(11);
        cpwaitg<0>(); body(12); body(13); body(14); body(15);
        __syncwarp();

        // ---------------- Phase 2: tensor-core logits ----------------
        float c1[2][4] = {{0.f, 0.f, 0.f, 0.f}, {0.f, 0.f, 0.f, 0.f}};
#pragma unroll
        for (int s = 0; s < 8; ++s) {
            unsigned a0 = wsm[(w * 16 + gid)     * 68 + 8 * s + tig];
            unsigned a1 = wsm[(w * 16 + gid + 8) * 68 + 8 * s + tig];
            unsigned a2 = wsm[(w * 16 + gid)     * 68 + 8 * s + tig + 4];
            unsigned a3 = wsm[(w * 16 + gid + 8) * 68 + 8 * s + tig + 4];
            mma_bf16(c1[0], a0, a1, a2, a3, bw1[s][0][0], bw1[s][0][1]);
            mma_bf16(c1[1], a0, a1, a2, a3, bw1[s][1][0], bw1[s][1][1]);
        }

        // BN2 + ReLU
        float t1[2][4];
#pragma unroll
        for (int b = 0; b < 2; ++b)
#pragma unroll
            for (int q = 0; q < 4; ++q)
                t1[b][q] = fmaxf(fmaf(c1[b][q], s2c[(q & 1) + 2 * b],
                                      b2c[(q & 1) + 2 * b]), 0.f);

        // permute c-frag -> A-frag for GEMV2
        const int srcA = 4 * gid + (tig >> 1);
        const bool oddt = (tig & 1);
        unsigned aa[2][4];
#pragma unroll
        for (int s = 0; s < 2; ++s) {
            float v0 = __shfl_sync(0xffffffffu, t1[s][0], srcA);
            float v1 = __shfl_sync(0xffffffffu, t1[s][1], srcA);
            float v2 = __shfl_sync(0xffffffffu, t1[s][2], srcA);
            float v3 = __shfl_sync(0xffffffffu, t1[s][3], srcA);
            float u0v = oddt ? v1 : v0;
            float u1v = oddt ? v3 : v2;
            float q0 = __shfl_sync(0xffffffffu, t1[s][0], srcA + 2);
            float q1 = __shfl_sync(0xffffffffu, t1[s][1], srcA + 2);
            float q2 = __shfl_sync(0xffffffffu, t1[s][2], srcA + 2);
            float q3 = __shfl_sync(0xffffffffu, t1[s][3], srcA + 2);
            float u2v = oddt ? q1 : q0;
            float u3v = oddt ? q3 : q2;
            aa[s][0] = f2tf32(u0v); aa[s][1] = f2tf32(u1v);
            aa[s][2] = f2tf32(u2v); aa[s][3] = f2tf32(u3v);
        }

        float c2[2][4] = {{0.f, 0.f, 0.f, 0.f}, {0.f, 0.f, 0.f, 0.f}};
#pragma unroll
        for (int s = 0; s < 2; ++s) {
            mma_tf32(c2[0], aa[s][0], aa[s][1], aa[s][2], aa[s][3],
                     w2f[s][0][0], w2f[s][0][1]);
            mma_tf32(c2[1], aa[s][0], aa[s][1], aa[s][2], aa[s][3],
                     w2f[s][1][0], w2f[s][1][1]);
        }

        // softmax over neighbors (fragment rows)
        float mx[2][2], Zs[2][2];
#pragma unroll
        for (int b = 0; b < 2; ++b) {
            mx[b][0] = fmaxf(c2[b][0], c2[b][2]);
            mx[b][1] = fmaxf(c2[b][1], c2[b][3]);
        }
#pragma unroll
        for (int msk = 4; msk <= 16; msk <<= 1)
#pragma unroll
            for (int b = 0; b < 2; ++b)
#pragma unroll
                for (int e = 0; e < 2; ++e)
                    mx[b][e] = fmaxf(mx[b][e],
                                     __shfl_xor_sync(0xffffffffu, mx[b][e], msk));
        float ev[2][4];
#pragma unroll
        for (int b = 0; b < 2; ++b)
#pragma unroll
            for (int q = 0; q < 4; ++q)
                ev[b][q] = exp2f(c2[b][q] - mx[b][q & 1]);
#pragma unroll
        for (int b = 0; b < 2; ++b) {
            Zs[b][0] = ev[b][0] + ev[b][2];
            Zs[b][1] = ev[b][1] + ev[b][3];
        }
#pragma unroll
        for (int msk = 4; msk <= 16; msk <<= 1)
#pragma unroll
            for (int b = 0; b < 2; ++b)
#pragma unroll
                for (int e = 0; e < 2; ++e)
                    Zs[b][e] += __shfl_xor_sync(0xffffffffu, Zs[b][e], msk);

        // exp weights transposed to wtb[o][n]
#pragma unroll
        for (int b = 0; b < 2; ++b)
#pragma unroll
            for (int q = 0; q < 4; ++q)
                wtb[(w * 16 + 2 * tig + (q & 1) + 8 * b) * 20 + gid + 8 * (q >> 1)] = ev[b][q];

        // unnormalized Z for this lane's column
        const int zsrc = (lane & 7) >> 1;
        float z00 = __shfl_sync(0xffffffffu, Zs[0][0], zsrc);
        float z01 = __shfl_sync(0xffffffffu, Zs[0][1], zsrc);
        float z10 = __shfl_sync(0xffffffffu, Zs[1][0], zsrc);
        float z11 = __shfl_sync(0xffffffffu, Zs[1][1], zsrc);
        float ze0 = (lane & 1) ? z01 : z00;
        float ze1 = (lane & 1) ? z11 : z10;
        float Zm  = (lane & 8) ? ze1 : ze0;
        float invZ = __frcp_rn(Zm);
        __syncwarp();

        // ------------- V accumulation from fp16 ring + tt fold -------------
        float Acc[4] = {0.f, 0.f, 0.f, 0.f};
        float st0 = 0.f, st1 = 0.f, st2 = 0.f;
#pragma unroll
        for (int h = 0; h < 4; ++h) {
            float4 wq4 = *(const float4*)&wtb[(w * 16 + o) * 20 + 4 * h];
#pragma unroll
            for (int j = 0; j < 4; ++j) {
                int n = 4 * h + j;
                float wn = (j == 0) ? wq4.x : (j == 1) ? wq4.y : (j == 2) ? wq4.z : wq4.w;
                ull vv = vrp[(n * 4 + w) * 32 + lane];
                unsigned vlo = (unsigned)vv, vhi = (unsigned)(vv >> 32);
                float2 f0 = __half22float2(*(const __half2*)&vlo);
                float2 f1 = __half22float2(*(const __half2*)&vhi);
                float4 t4 = ttb[w * 16 + n];
                Acc[0] = fmaf(wn, f0.x, Acc[0]);
                Acc[1] = fmaf(wn, f0.y, Acc[1]);
                Acc[2] = fmaf(wn, f1.x, Acc[2]);
                Acc[3] = fmaf(wn, f1.y, Acc[3]);
                st0 = fmaf(wn, t4.x, st0);
                st1 = fmaf(wn, t4.y, st1);
                st2 = fmaf(wn, t4.z, st2);
            }
        }

#pragma unroll
        for (int r = 0; r < 4; ++r) {
            float pesum = fmaf(pw2v[r][2], st2,
                          fmaf(pw2v[r][1], st1,
                          fmaf(pw2v[r][0], st0, pb2v[r] * Zm)));
            out[(size_t)i * CH + lane + 32 * r] = (Acc[r] + pesum) * invZ;
        }
    }
}

// ---------------------------------------------------------------------------
extern "C" void kernel_launch(void* const* d_in, const int* in_sizes, int n_in,
                              void* d_out, int out_size)
{
    const float* p    = (const float*)d_in[0];
    const float* x    = (const float*)d_in[1];
    const int*   idx  = (const int*)  d_in[2];
    const float* wq   = (const float*)d_in[3];
    const float* bq   = (const float*)d_in[4];
    const float* wk   = (const float*)d_in[5];
    const float* bk   = (const float*)d_in[6];
    const float* wv   = (const float*)d_in[7];
    const float* bv   = (const float*)d_in[8];
    const float* pw1  = (const float*)d_in[9];
    const float* pb1  = (const float*)d_in[10];
    const float* pbng = (const float*)d_in[11];
    const float* pbnb = (const float*)d_in[12];
    const float* pbnm = (const float*)d_in[13];
    const float* pbnv = (const float*)d_in[14];
    const float* pw2  = (const float*)d_in[15];
    const float* pb2  = (const float*)d_in[16];
    const float* bn1g = (const float*)d_in[17];
    const float* bn1b = (const float*)d_in[18];
    const float* bn1m = (const float*)d_in[19];
    const float* bn1v = (const float*)d_in[20];
    const float* ww1  = (const float*)d_in[21];
    const float* wb1  = (const float*)d_in[22];
    const float* bn2g = (const float*)d_in[23];
    const float* bn2b = (const float*)d_in[24];
    const float* bn2m = (const float*)d_in[25];
    const float* bn2v = (const float*)d_in[26];
    const float* ww2  = (const float*)d_in[27];
    const float* wb2  = (const float*)d_in[28];
    float* out = (float*)d_out;

    cudaFuncSetAttribute(attn_kernel,
                         cudaFuncAttributeMaxDynamicSharedMemorySize, SMEM_ATTN);

    qkv_tc_kernel<<<dim3(NPTS / 128, 4), 256>>>(x, p, wq, bq, wk, bk, wv, bv);

    attn_kernel<<<NPTS / (PPW * 4), 128, SMEM_ATTN>>>(
        idx,
        pw1, pb1, pbng, pbnb, pbnm, pbnv, pw2, pb2,
        bn1g, bn1b, bn1m, bn1v, ww1, wb1,
        bn2g, bn2b, bn2m, bn2v, ww2, wb2,
        out);
}

// round 17
// speedup vs baseline: 1.1794x; 1.0300x over previous
#include <cuda_runtime.h>
#include <cuda_fp16.h>
#include <math.h>

#define NPTS 65536
#define NS   16
#define CH   128
#define EPSB 1e-5f
#define LOG2E 1.4426950408889634f

typedef unsigned long long ull;

__device__ __forceinline__ void cpasync8(unsigned dst, const void* src) {
    asm volatile("cp.async.ca.shared.global [%0],[%1],8;" :: "r"(dst), "l"(src));
}
__device__ __forceinline__ void cpcommit() {
    asm volatile("cp.async.commit_group;");
}
template<int N> __device__ __forceinline__ void cpwaitg() {
    asm volatile("cp.async.wait_group %0;" :: "n"(N));
}
__device__ __forceinline__ unsigned f2tf32(float f) {
    unsigned u; asm("cvt.rna.tf32.f32 %0,%1;" : "=r"(u) : "f"(f)); return u;
}
__device__ __forceinline__ unsigned bf16x2hl(float hi, float lo) {
    unsigned d; asm("cvt.rn.bf16x2.f32 %0,%1,%2;" : "=r"(d) : "f"(hi), "f"(lo)); return d;
}
__device__ __forceinline__ unsigned f16x2hl(float hi, float lo) {
    unsigned d; asm("cvt.rn.f16x2.f32 %0,%1,%2;" : "=r"(d) : "f"(hi), "f"(lo)); return d;
}
__device__ __forceinline__ float bflo(unsigned u) {
    return __uint_as_float(u << 16);
}
__device__ __forceinline__ float bfhi(unsigned u) {
    return __uint_as_float(u & 0xffff0000u);
}
__device__ __forceinline__ void mma_tf32(float c[4],
                                         unsigned a0, unsigned a1,
                                         unsigned a2, unsigned a3,
                                         unsigned b0, unsigned b1) {
    asm("mma.sync.aligned.m16n8k8.row.col.f32.tf32.tf32.f32 "
        "{%0,%1,%2,%3},{%4,%5,%6,%7},{%8,%9},{%0,%1,%2,%3};"
        : "+f"(c[0]), "+f"(c[1]), "+f"(c[2]), "+f"(c[3])
        : "r"(a0), "r"(a1), "r"(a2), "r"(a3), "r"(b0), "r"(b1));
}
__device__ __forceinline__ void mma_f16(float c[4],
                                        unsigned a0, unsigned a1,
                                        unsigned a2, unsigned a3,
                                        unsigned b0, unsigned b1) {
    asm("mma.sync.aligned.m16n8k16.row.col.f32.f16.f16.f32 "
        "{%0,%1,%2,%3},{%4,%5,%6,%7},{%8,%9},{%0,%1,%2,%3};"
        : "+f"(c[0]), "+f"(c[1]), "+f"(c[2]), "+f"(c[3])
        : "r"(a0), "r"(a1), "r"(a2), "r"(a3), "r"(b0), "r"(b1));
}
__device__ __forceinline__ void mma_bf16(float c[4],
                                         unsigned a0, unsigned a1,
                                         unsigned a2, unsigned a3,
                                         unsigned b0, unsigned b1) {
    asm("mma.sync.aligned.m16n8k16.row.col.f32.bf16.bf16.f32 "
        "{%0,%1,%2,%3},{%4,%5,%6,%7},{%8,%9},{%0,%1,%2,%3};"
        : "+f"(c[0]), "+f"(c[1]), "+f"(c[2]), "+f"(c[3])
        : "r"(a0), "r"(a1), "r"(a2), "r"(a3), "r"(b0), "r"(b1));
}

// static device scratch (allocation-guard safe)
__device__ float  g_q [(size_t)NPTS * CH];
__device__ ull    g_kb[(size_t)NPTS * 32];   // bf16 K packed: 256B/point
__device__ ull    g_vh[(size_t)NPTS * 32];   // fp16 V packed: 256B/point
__device__ float4 g_p4[NPTS];

// ---------------------------------------------------------------------------
// Kernel 1: QKV GEMM on fp16 tensor cores, register-prefetch double buffering
// (LDG for chunk c+1 issued while mma runs on chunk c).
// grid (512, 4): y<3 -> q/k/v GEMM; y==3 -> position packing.
// ---------------------------------------------------------------------------
__global__ void __launch_bounds__(256)
qkv_tc_kernel(const float* __restrict__ x, const float* __restrict__ p,
              const float* __restrict__ wq, const float* __restrict__ bq,
              const float* __restrict__ wk, const float* __restrict__ bk,
              const float* __restrict__ wv, const float* __restrict__ bv)
{
    __shared__ unsigned Xh[128][20];
    __shared__ unsigned Wh[128][20];

    const int sel = blockIdx.y;
    if (sel == 3) {
        int i = blockIdx.x * 128 + (threadIdx.x & 127);
        if (threadIdx.x < 128)
            g_p4[i] = make_float4(p[3 * i + 0], p[3 * i + 1], p[3 * i + 2], 0.f);
        return;
    }

    const float* W;
    const float* bias;
    if (sel == 0)      { W = wq; bias = bq; }
    else if (sel == 1) { W = wk; bias = bk; }
    else               { W = wv; bias = bv; }

    const int tid  = threadIdx.x;
    const int warp = tid >> 5;
    const int lane = tid & 31;
    const int gid  = lane >> 2;
    const int tig  = lane & 3;
    const int m0   = blockIdx.x * 128;
    const int r0   = warp * 16;

    const int srow = tid >> 1;
    const int skq  = (tid & 1) * 16;
    const int p0   = (tid & 1) * 8;

    float c[16][4];
#pragma unroll
    for (int nb = 0; nb < 16; ++nb)
#pragma unroll
        for (int j = 0; j < 4; ++j) c[nb][j] = 0.f;

    // prefetch chunk 0 into registers
    float4 xr[4], wr[4];
#pragma unroll
    for (int i = 0; i < 4; ++i) {
        xr[i] = *(const float4*)&x[(size_t)(m0 + srow) * 128 + skq + 4 * i];
        wr[i] = *(const float4*)&W[(size_t)srow * 128 + skq + 4 * i];
    }

#pragma unroll 1
    for (int ch = 0; ch < 4; ++ch) {
        // stage prefetched registers into smem (f16x2 pairs)
        {
            float xv[16], wv[16];
#pragma unroll
            for (int i = 0; i < 4; ++i) {
                xv[4 * i] = xr[i].x; xv[4 * i + 1] = xr[i].y;
                xv[4 * i + 2] = xr[i].z; xv[4 * i + 3] = xr[i].w;
                wv[4 * i] = wr[i].x; wv[4 * i + 1] = wr[i].y;
                wv[4 * i + 2] = wr[i].z; wv[4 * i + 3] = wr[i].w;
            }
            uint4 xo0, xo1, wo0, wo1;
            xo0.x = f16x2hl(xv[1],  xv[0]);  xo0.y = f16x2hl(xv[3],  xv[2]);
            xo0.z = f16x2hl(xv[5],  xv[4]);  xo0.w = f16x2hl(xv[7],  xv[6]);
            xo1.x = f16x2hl(xv[9],  xv[8]);  xo1.y = f16x2hl(xv[11], xv[10]);
            xo1.z = f16x2hl(xv[13], xv[12]); xo1.w = f16x2hl(xv[15], xv[14]);
            wo0.x = f16x2hl(wv[1],  wv[0]);  wo0.y = f16x2hl(wv[3],  wv[2]);
            wo0.z = f16x2hl(wv[5],  wv[4]);  wo0.w = f16x2hl(wv[7],  wv[6]);
            wo1.x = f16x2hl(wv[9],  wv[8]);  wo1.y = f16x2hl(wv[11], wv[10]);
            wo1.z = f16x2hl(wv[13], wv[12]); wo1.w = f16x2hl(wv[15], wv[14]);
            *(uint4*)&Xh[srow][p0]     = xo0;
            *(uint4*)&Xh[srow][p0 + 4] = xo1;
            *(uint4*)&Wh[srow][p0]     = wo0;
            *(uint4*)&Wh[srow][p0 + 4] = wo1;
        }
        __syncthreads();

        // prefetch next chunk while mma runs on this one
        if (ch < 3) {
            const int kc = (ch + 1) * 32;
#pragma unroll
            for (int i = 0; i < 4; ++i) {
                xr[i] = *(const float4*)&x[(size_t)(m0 + srow) * 128 + kc + skq + 4 * i];
                wr[i] = *(const float4*)&W[(size_t)srow * 128 + kc + skq + 4 * i];
            }
        }

#pragma unroll
        for (int ks = 0; ks < 2; ++ks) {
            const int pb = 8 * ks;
            unsigned a0 = Xh[r0 + gid][pb + tig];
            unsigned a1 = Xh[r0 + gid + 8][pb + tig];
            unsigned a2 = Xh[r0 + gid][pb + tig + 4];
            unsigned a3 = Xh[r0 + gid + 8][pb + tig + 4];
#pragma unroll
            for (int nb = 0; nb < 16; ++nb) {
                unsigned b0 = Wh[nb * 8 + gid][pb + tig];
                unsigned b1 = Wh[nb * 8 + gid][pb + tig + 4];
                mma_f16(c[nb], a0, a1, a2, a3, b0, b1);
            }
        }
        __syncthreads();
    }

    if (sel == 0) {
#pragma unroll
        for (int nb = 0; nb < 16; ++nb) {
            const int col = nb * 8 + 2 * tig;
            const float2 bv = *(const float2*)&bias[col];
            const size_t row = (size_t)(m0 + r0 + gid);
            *(float2*)&g_q[row * 128 + col] =
                make_float2(c[nb][0] + bv.x, c[nb][1] + bv.y);
            *(float2*)&g_q[(row + 8) * 128 + col] =
                make_float2(c[nb][2] + bv.x, c[nb][3] + bv.y);
        }
    } else if (sel == 1) {
        // K: bf16 packed per lane-slot l: {(k(l),k(l+32)),(k(l+64),k(l+96))}
#pragma unroll
        for (int nb = 0; nb < 4; ++nb)
#pragma unroll
            for (int e = 0; e < 2; ++e) {
                const int l = nb * 8 + 2 * tig + e;
                const float b0 = bias[l], b1 = bias[l + 32];
                const float b2 = bias[l + 64], b3 = bias[l + 96];
                unsigned lo = bf16x2hl(c[nb + 4][e] + b1, c[nb][e] + b0);
                unsigned hi = bf16x2hl(c[nb + 12][e] + b3, c[nb + 8][e] + b2);
                g_kb[(size_t)(m0 + r0 + gid) * 32 + l] = ((ull)hi << 32) | lo;
                unsigned lo2 = bf16x2hl(c[nb + 4][e + 2] + b1, c[nb][e + 2] + b0);
                unsigned hi2 = bf16x2hl(c[nb + 12][e + 2] + b3, c[nb + 8][e + 2] + b2);
                g_kb[(size_t)(m0 + r0 + gid + 8) * 32 + l] = ((ull)hi2 << 32) | lo2;
            }
    } else {
        // V: fp16 packed, same layout as K
#pragma unroll
        for (int nb = 0; nb < 4; ++nb)
#pragma unroll
            for (int e = 0; e < 2; ++e) {
                const int l = nb * 8 + 2 * tig + e;
                const float b0 = bias[l], b1 = bias[l + 32];
                const float b2 = bias[l + 64], b3 = bias[l + 96];
                unsigned lo = f16x2hl(c[nb + 4][e] + b1, c[nb][e] + b0);
                unsigned hi = f16x2hl(c[nb + 12][e] + b3, c[nb + 8][e] + b2);
                g_vh[(size_t)(m0 + r0 + gid) * 32 + l] = ((ull)hi << 32) | lo;
                unsigned lo2 = f16x2hl(c[nb + 4][e + 2] + b1, c[nb][e + 2] + b0);
                unsigned hi2 = f16x2hl(c[nb + 12][e + 2] + b3, c[nb + 8][e + 2] + b2);
                g_vh[(size_t)(m0 + r0 + gid + 8) * 32 + l] = ((ull)hi2 << 32) | lo2;
            }
    }
}

// ---------------------------------------------------------------------------
// Kernel 2: tensor-core attention (R15/R16-exact).
// ---------------------------------------------------------------------------
#define PPW 8
// smem offsets (bytes)
#define OFF_KR  0        // ull [16][4][32]       = 16384
#define OFF_VR  16384    // ull [16][4][32]       = 16384
#define OFF_WSM 32768    // unsigned [4][16][68]  = 17408
#define OFF_TT  50176    // float4 [4][16]        = 1024
#define OFF_WT  51200    // float [4][16][20]     = 5120
#define SMEM_ATTN 56320

__global__ void __launch_bounds__(128, 4)
attn_kernel(const int* __restrict__ idx,
            const float* __restrict__ pw1, const float* __restrict__ pb1,
            const float* __restrict__ pbng, const float* __restrict__ pbnb,
            const float* __restrict__ pbnm, const float* __restrict__ pbnv,
            const float* __restrict__ pw2, const float* __restrict__ pb2,
            const float* __restrict__ bn1g, const float* __restrict__ bn1b,
            const float* __restrict__ bn1m, const float* __restrict__ bn1v,
            const float* __restrict__ ww1, const float* __restrict__ wb1,
            const float* __restrict__ bn2g, const float* __restrict__ bn2b,
            const float* __restrict__ bn2m, const float* __restrict__ bn2v,
            const float* __restrict__ ww2, const float* __restrict__ wb2,
            float* __restrict__ out)
{
    extern __shared__ char dsm[];
    ull*      krp = (ull*)(dsm + OFF_KR);
    ull*      vrp = (ull*)(dsm + OFF_VR);
    unsigned* wsm = (unsigned*)(dsm + OFF_WSM);
    float4*   ttb = (float4*)(dsm + OFF_TT);
    float*    wtb = (float*)(dsm + OFF_WT);

    const int lane = threadIdx.x & 31;
    const int w    = (threadIdx.x >> 5) & 3;
    const int gw   = blockIdx.x * (blockDim.x >> 5) + (threadIdx.x >> 5);
    const int gid  = lane >> 2;
    const int tig  = lane & 3;
    const int o    = lane & 15;

    // W1 bf16 B-fragments (R9-proven mapping)
    unsigned bw1[8][2][2];
#pragma unroll
    for (int s = 0; s < 8; ++s)
#pragma unroll
        for (int b = 0; b < 2; ++b)
#pragma unroll
            for (int j = 0; j < 2; ++j) {
                int pp = 8 * s + tig + 4 * j;
                int c = (pp < 32) ? pp : pp + 32;
                int oo = 8 * b + gid;
                bw1[s][b][j] = bf16x2hl(ww1[oo * CH + c + 32], ww1[oo * CH + c]);
            }

    // W2 tf32 B-fragments (LOG2E folded)
    unsigned w2f[2][2][2];
#pragma unroll
    for (int s = 0; s < 2; ++s)
#pragma unroll
        for (int b = 0; b < 2; ++b)
#pragma unroll
            for (int j = 0; j < 2; ++j) {
                int u = 8 * s + tig + 4 * j;
                int oo = 8 * b + gid;
                w2f[s][b][j] = f2tf32(ww2[oo * 16 + u] * LOG2E);
            }

    // BN2 constants on c-frag cols
    float s2c[4], b2c[4];
#pragma unroll
    for (int j = 0; j < 4; ++j) {
        int u = 2 * tig + (j & 1) + 8 * (j >> 1);
        float s = bn2g[u] * rsqrtf(bn2v[u] + EPSB);
        s2c[j] = s;
        b2c[j] = bn2b[u] - bn2m[u] * s + wb1[u] * s;
    }

    float s1[4], b1f[4], pw2v[4][3], pb2v[4];
#pragma unroll
    for (int r = 0; r < 4; ++r) {
        int c = lane + 32 * r;
        float s = bn1g[c] * rsqrtf(bn1v[c] + EPSB);
        s1[r]  = s;
        b1f[r] = bn1b[c] - bn1m[c] * s;
        pw2v[r][0] = pw2[c * 3 + 0];
        pw2v[r][1] = pw2[c * 3 + 1];
        pw2v[r][2] = pw2[c * 3 + 2];
        pb2v[r] = pb2[c];
    }
    float Af[9], df[3];
#pragma unroll
    for (int a = 0; a < 3; ++a) {
        float s  = pbng[a] * rsqrtf(pbnv[a] + EPSB);
        float sh = pbnb[a] - pbnm[a] * s;
#pragma unroll
        for (int b = 0; b < 3; ++b) Af[a * 3 + b] = s * pw1[a * 3 + b];
        df[a] = s * pb1[a] + sh;
    }

    const unsigned kr0 =
        (unsigned)__cvta_generic_to_shared(&krp[w * 32 + lane]);
    const unsigned vr0 =
        (unsigned)__cvta_generic_to_shared(&vrp[w * 32 + lane]);

#pragma unroll 1
    for (int t = 0; t < PPW; ++t) {
        const int i = gw * PPW + t;

        const float4 pi = g_p4[i];
        float xqf[4];
#pragma unroll
        for (int r = 0; r < 4; ++r) {
            float xq = g_q[(size_t)i * CH + lane + 32 * r];
            xqf[r] = b1f[r] - s1[r] * xq;
        }
        const int myj = idx[i * NS + o];
        const float4 pjall = g_p4[myj];

        // issue all 16 neighbors' K+V loads (4 commit groups of 4 neighbors)
#pragma unroll
        for (int g = 0; g < 4; ++g) {
#pragma unroll
            for (int e = 0; e < 4; ++e) {
                int n = 4 * g + e;
                int js = __shfl_sync(0xffffffffu, myj, n);
                cpasync8(kr0 + (unsigned)n * 1024u, &g_kb[(size_t)js * 32 + lane]);
                cpasync8(vr0 + (unsigned)n * 1024u, &g_vh[(size_t)js * 32 + lane]);
            }
            cpcommit();
        }

        // ---------------- Phase 1: consume K, build wsm + ttb ----------------
        auto body = [&](int n) {
            ull kk = krp[(n * 4 + w) * 32 + lane];
            unsigned klo = (unsigned)kk, khi = (unsigned)(kk >> 32);
            float gk[4] = {bflo(klo), bfhi(klo), bflo(khi), bfhi(khi)};
            float pr0 = __shfl_sync(0xffffffffu, pjall.x, n) - pi.x;
            float pr1 = __shfl_sync(0xffffffffu, pjall.y, n) - pi.y;
            float pr2 = __shfl_sync(0xffffffffu, pjall.z, n) - pi.z;

            float tt[3];
#pragma unroll
            for (int a = 0; a < 3; ++a) {
                float v = fmaf(pr2, Af[a * 3 + 2],
                          fmaf(pr1, Af[a * 3 + 1],
                          fmaf(pr0, Af[a * 3 + 0], df[a])));
                tt[a] = fmaxf(v, 0.f);
            }
            if (lane == 0)
                ttb[w * 16 + n] = make_float4(tt[0], tt[1], tt[2], 0.f);

            float wp[4];
#pragma unroll
            for (int r = 0; r < 4; ++r) {
                float pe = fmaf(tt[2], pw2v[r][2],
                           fmaf(tt[1], pw2v[r][1],
                           fmaf(tt[0], pw2v[r][0], pb2v[r])));
                wp[r] = fmaxf(fmaf(gk[r] + pe, s1[r], xqf[r]), 0.f);
            }
            wsm[(w * 16 + n) * 68 + lane]      = bf16x2hl(wp[1], wp[0]);
            wsm[(w * 16 + n) * 68 + 32 + lane] = bf16x2hl(wp[3], wp[2]);
        };
        cpwaitg<3>(); body(0);  body(1);  body(2);  body(3);
        cpwaitg<2>(); body(4);  body(5);  body(6);  body(7);
        cpwaitg<1>(); body(8);  body(9);  body(10); body(11);
        cpwaitg<0>(); body(12); body(13); body(14); body(15);
        __syncwarp();

        // ---------------- Phase 2: tensor-core logits ----------------
        float c1[2][4] = {{0.f, 0.f, 0.f, 0.f}, {0.f, 0.f, 0.f, 0.f}};
#pragma unroll
        for (int s = 0; s < 8; ++s) {
            unsigned a0 = wsm[(w * 16 + gid)     * 68 + 8 * s + tig];
            unsigned a1 = wsm[(w * 16 + gid + 8) * 68 + 8 * s + tig];
            unsigned a2 = wsm[(w * 16 + gid)     * 68 + 8 * s + tig + 4];
            unsigned a3 = wsm[(w * 16 + gid + 8) * 68 + 8 * s + tig + 4];
            mma_bf16(c1[0], a0, a1, a2, a3, bw1[s][0][0], bw1[s][0][1]);
            mma_bf16(c1[1], a0, a1, a2, a3, bw1[s][1][0], bw1[s][1][1]);
        }

        // BN2 + ReLU
        float t1[2][4];
#pragma unroll
        for (int b = 0; b < 2; ++b)
#pragma unroll
            for (int q = 0; q < 4; ++q)
                t1[b][q] = fmaxf(fmaf(c1[b][q], s2c[(q & 1) + 2 * b],
                                      b2c[(q & 1) + 2 * b]), 0.f);

        // permute c-frag -> A-frag for GEMV2
        const int srcA = 4 * gid + (tig >> 1);
        const bool oddt = (tig & 1);
        unsigned aa[2][4];
#pragma unroll
        for (int s = 0; s < 2; ++s) {
            float v0 = __shfl_sync(0xffffffffu, t1[s][0], srcA);
            float v1 = __shfl_sync(0xffffffffu, t1[s][1], srcA);
            float v2 = __shfl_sync(0xffffffffu, t1[s][2], srcA);
            float v3 = __shfl_sync(0xffffffffu, t1[s][3], srcA);
            float u0v = oddt ? v1 : v0;
            float u1v = oddt ? v3 : v2;
            float q0 = __shfl_sync(0xffffffffu, t1[s][0], srcA + 2);
            float q1 = __shfl_sync(0xffffffffu, t1[s][1], srcA + 2);
            float q2 = __shfl_sync(0xffffffffu, t1[s][2], srcA + 2);
            float q3 = __shfl_sync(0xffffffffu, t1[s][3], srcA + 2);
            float u2v = oddt ? q1 : q0;
            float u3v = oddt ? q3 : q2;
            aa[s][0] = f2tf32(u0v); aa[s][1] = f2tf32(u1v);
            aa[s][2] = f2tf32(u2v); aa[s][3] = f2tf32(u3v);
        }

        float c2[2][4] = {{0.f, 0.f, 0.f, 0.f}, {0.f, 0.f, 0.f, 0.f}};
#pragma unroll
        for (int s = 0; s < 2; ++s) {
            mma_tf32(c2[0], aa[s][0], aa[s][1], aa[s][2], aa[s][3],
                     w2f[s][0][0], w2f[s][0][1]);
            mma_tf32(c2[1], aa[s][0], aa[s][1], aa[s][2], aa[s][3],
                     w2f[s][1][0], w2f[s][1][1]);
        }

        // softmax over neighbors (fragment rows)
        float mx[2][2], Zs[2][2];
#pragma unroll
        for (int b = 0; b < 2; ++b) {
            mx[b][0] = fmaxf(c2[b][0], c2[b][2]);
            mx[b][1] = fmaxf(c2[b][1], c2[b][3]);
        }
#pragma unroll
        for (int msk = 4; msk <= 16; msk <<= 1)
#pragma unroll
            for (int b = 0; b < 2; ++b)
#pragma unroll
                for (int e = 0; e < 2; ++e)
                    mx[b][e] = fmaxf(mx[b][e],
                                     __shfl_xor_sync(0xffffffffu, mx[b][e], msk));
        float ev[2][4];
#pragma unroll
        for (int b = 0; b < 2; ++b)
#pragma unroll
            for (int q = 0; q < 4; ++q)
                ev[b][q] = exp2f(c2[b][q] - mx[b][q & 1]);
#pragma unroll
        for (int b = 0; b < 2; ++b) {
            Zs[b][0] = ev[b][0] + ev[b][2];
            Zs[b][1] = ev[b][1] + ev[b][3];
        }
#pragma unroll
        for (int msk = 4; msk <= 16; msk <<= 1)
#pragma unroll
            for (int b = 0; b < 2; ++b)
#pragma unroll
                for (int e = 0; e < 2; ++e)
                    Zs[b][e] += __shfl_xor_sync(0xffffffffu, Zs[b][e], msk);

        // exp weights transposed to wtb[o][n]
#pragma unroll
        for (int b = 0; b < 2; ++b)
#pragma unroll
            for (int q = 0; q < 4; ++q)
                wtb[(w * 16 + 2 * tig + (q & 1) + 8 * b) * 20 + gid + 8 * (q >> 1)] = ev[b][q];

        // unnormalized Z for this lane's column
        const int zsrc = (lane & 7) >> 1;
        float z00 = __shfl_sync(0xffffffffu, Zs[0][0], zsrc);
        float z01 = __shfl_sync(0xffffffffu, Zs[0][1], zsrc);
        float z10 = __shfl_sync(0xffffffffu, Zs[1][0], zsrc);
        float z11 = __shfl_sync(0xffffffffu, Zs[1][1], zsrc);
        float ze0 = (lane & 1) ? z01 : z00;
        float ze1 = (lane & 1) ? z11 : z10;
        float Zm  = (lane & 8) ? ze1 : ze0;
        float invZ = __frcp_rn(Zm);
        __syncwarp();

        // ------------- V accumulation from fp16 ring + tt fold -------------
        float Acc[4] = {0.f, 0.f, 0.f, 0.f};
        float st0 = 0.f, st1 = 0.f, st2 = 0.f;
#pragma unroll
        for (int h = 0; h < 4; ++h) {
            float4 wq4 = *(const float4*)&wtb[(w * 16 + o) * 20 + 4 * h];
#pragma unroll
            for (int j = 0; j < 4; ++j) {
                int n = 4 * h + j;
                float wn = (j == 0) ? wq4.x : (j == 1) ? wq4.y : (j == 2) ? wq4.z : wq4.w;
                ull vv = vrp[(n * 4 + w) * 32 + lane];
                unsigned vlo = (unsigned)vv, vhi = (unsigned)(vv >> 32);
                float2 f0 = __half22float2(*(const __half2*)&vlo);
                float2 f1 = __half22float2(*(const __half2*)&vhi);
                float4 t4 = ttb[w * 16 + n];
                Acc[0] = fmaf(wn, f0.x, Acc[0]);
                Acc[1] = fmaf(wn, f0.y, Acc[1]);
                Acc[2] = fmaf(wn, f1.x, Acc[2]);
                Acc[3] = fmaf(wn, f1.y, Acc[3]);
                st0 = fmaf(wn, t4.x, st0);
                st1 = fmaf(wn, t4.y, st1);
                st2 = fmaf(wn, t4.z, st2);
            }
        }

#pragma unroll
        for (int r = 0; r < 4; ++r) {
            float pesum = fmaf(pw2v[r][2], st2,
                          fmaf(pw2v[r][1], st1,
                          fmaf(pw2v[r][0], st0, pb2v[r] * Zm)));
            out[(size_t)i * CH + lane + 32 * r] = (Acc[r] + pesum) * invZ;
        }
    }
}

// ---------------------------------------------------------------------------
extern "C" void kernel_launch(void* const* d_in, const int* in_sizes, int n_in,
                              void* d_out, int out_size)
{
    const float* p    = (const float*)d_in[0];
    const float* x    = (const float*)d_in[1];
    const int*   idx  = (const int*)  d_in[2];
    const float* wq   = (const float*)d_in[3];
    const float* bq   = (const float*)d_in[4];
    const float* wk   = (const float*)d_in[5];
    const float* bk   = (const float*)d_in[6];
    const float* wv   = (const float*)d_in[7];
    const float* bv   = (const float*)d_in[8];
    const float* pw1  = (const float*)d_in[9];
    const float* pb1  = (const float*)d_in[10];
    const float* pbng = (const float*)d_in[11];
    const float* pbnb = (const float*)d_in[12];
    const float* pbnm = (const float*)d_in[13];
    const float* pbnv = (const float*)d_in[14];
    const float* pw2  = (const float*)d_in[15];
    const float* pb2  = (const float*)d_in[16];
    const float* bn1g = (const float*)d_in[17];
    const float* bn1b = (const float*)d_in[18];
    const float* bn1m = (const float*)d_in[19];
    const float* bn1v = (const float*)d_in[20];
    const float* ww1  = (const float*)d_in[21];
    const float* wb1  = (const float*)d_in[22];
    const float* bn2g = (const float*)d_in[23];
    const float* bn2b = (const float*)d_in[24];
    const float* bn2m = (const float*)d_in[25];
    const float* bn2v = (const float*)d_in[26];
    const float* ww2  = (const float*)d_in[27];
    const float* wb2  = (const float*)d_in[28];
    float* out = (float*)d_out;

    cudaFuncSetAttribute(attn_kernel,
                         cudaFuncAttributeMaxDynamicSharedMemorySize, SMEM_ATTN);

    qkv_tc_kernel<<<dim3(NPTS / 128, 4), 256>>>(x, p, wq, bq, wk, bk, wv, bv);

    attn_kernel<<<NPTS / (PPW * 4), 128, SMEM_ATTN>>>(
        idx,
        pw1, pb1, pbng, pbnb, pbnm, pbnv, pw2, pb2,
        bn1g, bn1b, bn1m, bn1v, ww1, wb1,
        bn2g, bn2b, bn2m, bn2v, ww2, wb2,
        out);
}